// round 11
// baseline (speedup 1.0000x reference)
#include <cuda_runtime.h>
#include <cuda_fp16.h>
#include <math.h>

#define Bb 32
#define Cc 256
#define Nn 4096
#define KD 64
#define HEADS 8
#define QD 512
#define OD 256

// ---------------- scratch (device globals; allocation-free) ----------------
__device__ __align__(256) __half g_kvh[(size_t)Bb*128*Nn];   // rows 0..63 exp(k), 64..127 v (half)
__device__ __align__(256) float  g_rowsum[Bb*KD];
__device__ __align__(256) float  g_ctx_part[(size_t)Bb*16*KD*KD];
__device__ __align__(256) float  g_ctx[(size_t)Bb*KD*KD];
__device__ __align__(256) __half g_Mh[(size_t)Bb*OD*QD];     // folded Wo*ctx, half
__device__ __align__(256) __half g_Wqh[QD*Cc];               // half Wq
__device__ __align__(256) __half g_Wkvh[128*Cc];             // half [Wk; Wv]

// ---------------- helpers ----------------
__device__ __forceinline__ void mma16h(float* d, const unsigned* a, const unsigned* b){
    asm volatile("mma.sync.aligned.m16n8k16.row.col.f32.f16.f16.f32 "
        "{%0,%1,%2,%3}, {%4,%5,%6,%7}, {%8,%9}, {%0,%1,%2,%3};"
        : "+f"(d[0]), "+f"(d[1]), "+f"(d[2]), "+f"(d[3])
        : "r"(a[0]), "r"(a[1]), "r"(a[2]), "r"(a[3]), "r"(b[0]), "r"(b[1]));
}
__device__ __forceinline__ void cpa16(void* smem_dst, const void* gsrc){
    unsigned s = (unsigned)__cvta_generic_to_shared(smem_dst);
    asm volatile("cp.async.cg.shared.global [%0], [%1], 16;" :: "r"(s), "l"(gsrc));
}
#define CP_COMMIT() asm volatile("cp.async.commit_group;")
#define CP_WAIT1()  asm volatile("cp.async.wait_group 1;")
#define CP_WAIT0()  asm volatile("cp.async.wait_group 0;")

__device__ __forceinline__ unsigned ldh2(const __half* p){ return *(const unsigned*)p; }

// ---------------- K0: convert weights to half ----------------
__global__ void __launch_bounds__(256) round_kernel(
    const float* __restrict__ Wq, const float* __restrict__ Wk, const float* __restrict__ Wv)
{
    int i = blockIdx.x*256 + threadIdx.x;
    if (i < QD*Cc) g_Wqh[i] = __float2half_rn(Wq[i]);
    if (i < KD*Cc) { g_Wkvh[i] = __float2half_rn(Wk[i]); g_Wkvh[KD*Cc + i] = __float2half_rn(Wv[i]); }
}

// ---------------- K1: kv projection (fp16 MMA) -> exp(k), v (half) ----------------
// grid (64 ntiles, 32 b), 256 thr. smem: xs half[64][264] + As half[2][128][40] = 54272 B
__global__ void __launch_bounds__(256) kv_proj_h(
    const float* __restrict__ x, const float* __restrict__ bk, const float* __restrict__ bv)
{
    extern __shared__ __half smk[];
    __half* xs = smk;                 // [n=64][c=264] (transposed, c contiguous)
    __half* As = smk + 64*264;        // [2][128][40]
    const int nt = blockIdx.x, b = blockIdx.y;
    const int n0 = nt*64;
    const int tid = threadIdx.x;
    const int warp = tid>>5, lane = tid&31;
    const int g = lane>>2, t4 = lane&3;
    const int wr = warp>>1, wc = warp&1;

    // load x tile [256 c][64 n], store transposed as half
    for (int i = tid; i < 256*16; i += 256) {
        int c = i>>4, n4 = (i&15)*4;
        float4 val = *(const float4*)(x + ((size_t)b*Cc + c)*Nn + n0 + n4);
        xs[(n4+0)*264 + c] = __float2half_rn(val.x);
        xs[(n4+1)*264 + c] = __float2half_rn(val.y);
        xs[(n4+2)*264 + c] = __float2half_rn(val.z);
        xs[(n4+3)*264 + c] = __float2half_rn(val.w);
    }
    // prefetch W chunk 0 (128 rows x 32 halves)
    #pragma unroll
    for (int j=0;j<2;j++){
        int s = tid + 256*j;             // 0..511
        int row = s>>2, seg = s&3;
        cpa16(As + row*40 + seg*8, g_Wkvh + row*Cc + seg*8);
    }
    CP_COMMIT();

    float acc[2][4][4];
    #pragma unroll
    for (int a=0;a<2;a++)
      #pragma unroll
      for (int c=0;c<4;c++)
        #pragma unroll
        for (int k=0;k<4;k++) acc[a][c][k]=0.f;

    const int NK = 8;   // 256 / 32
    for (int kc=0; kc<NK; kc++){
        if (kc+1 < NK){
            __half* dst = As + ((kc+1)&1)*5120;
            const __half* src = g_Wkvh + (kc+1)*32;
            #pragma unroll
            for (int j=0;j<2;j++){
                int s = tid + 256*j;
                int row = s>>2, seg = s&3;
                cpa16(dst + row*40 + seg*8, src + row*Cc + seg*8);
            }
            CP_COMMIT(); CP_WAIT1();
        } else CP_WAIT0();
        __syncthreads();
        const __half* A0 = As + (kc&1)*5120 + (wr*32)*40;
        #pragma unroll
        for (int sub=0; sub<2; sub++){
            int kl = sub*16 + t4*2;
            int kabs = kc*32 + kl;
            unsigned bf[4][2];
            #pragma unroll
            for (int n8=0;n8<4;n8++){
                int n = wc*32 + n8*8 + g;
                bf[n8][0] = ldh2(xs + n*264 + kabs);
                bf[n8][1] = ldh2(xs + n*264 + kabs + 8);
            }
            #pragma unroll
            for (int mt=0;mt<2;mt++){
                const __half* Ap = A0 + (mt*16 + g)*40 + kl;
                unsigned af[4];
                af[0] = ldh2(Ap);
                af[1] = ldh2(Ap + 8*40);
                af[2] = ldh2(Ap + 8);
                af[3] = ldh2(Ap + 8*40 + 8);
                #pragma unroll
                for (int n8=0;n8<4;n8++) mma16h(acc[mt][n8], af, bf[n8]);
            }
        }
        __syncthreads();
    }
    // epilogue: bias, exp for k-rows, store half2
    #pragma unroll
    for (int mt=0;mt<2;mt++){
        int r0 = wr*32 + mt*16 + g;
        int r1 = r0 + 8;
        bool isk = (r0 < 64);
        float bi0 = isk ? bk[r0] : bv[r0-64];
        float bi1 = isk ? bk[r1] : bv[r1-64];
        #pragma unroll
        for (int n8=0;n8<4;n8++){
            int c = n0 + wc*32 + n8*8 + 2*t4;
            float v00 = acc[mt][n8][0]+bi0, v01 = acc[mt][n8][1]+bi0;
            float v10 = acc[mt][n8][2]+bi1, v11 = acc[mt][n8][3]+bi1;
            if (isk){ v00=__expf(v00); v01=__expf(v01); v10=__expf(v10); v11=__expf(v11); }
            *(__half2*)(g_kvh + ((size_t)b*128 + r0)*Nn + c) = __floats2half2_rn(v00, v01);
            *(__half2*)(g_kvh + ((size_t)b*128 + r1)*Nn + c) = __floats2half2_rn(v10, v11);
        }
    }
}

// ---------------- K2: row sums of exp(k) ----------------
__global__ void __launch_bounds__(256) rowsum_kernel()
{
    int d = blockIdx.x, b = blockIdx.y;
    const __half2* row = (const __half2*)(g_kvh + ((size_t)b*128 + d)*Nn);
    __shared__ float red[256];
    float s = 0.f;
    for (int i = threadIdx.x; i < Nn/2; i += 256){
        float2 f = __half22float2(row[i]);
        s += f.x + f.y;
    }
    red[threadIdx.x] = s; __syncthreads();
    for (int st=128; st>0; st>>=1){
        if (threadIdx.x < st) red[threadIdx.x] += red[threadIdx.x+st];
        __syncthreads();
    }
    if (threadIdx.x == 0) g_rowsum[b*KD+d] = red[0];
}

// ---------------- K3a: ctx partials via fp16 MMA ----------------
// grid (16 splits, 32 b), 128 thr. smem: ts[2][128][72] half = 36864 B (16B aligned for cp.async)
__global__ void __launch_bounds__(128) ctx_part_h()
{
    __shared__ __align__(16) __half ts[2][128][72];
    const int sp = blockIdx.x, b = blockIdx.y;
    const int tid = threadIdx.x;
    const int warp = tid>>5, lane = tid&31;
    const int g = lane>>2, t4 = lane&3;
    const size_t base = (size_t)b*128*Nn + sp*256;

    // prefetch chunk 0: 128 rows x 64 halves
    #pragma unroll
    for (int j=0;j<8;j++){
        int s = tid + 128*j;             // 0..1023
        int row = s>>3, seg = s&7;
        cpa16(&ts[0][row][seg*8], g_kvh + base + (size_t)row*Nn + seg*8);
    }
    CP_COMMIT();

    float acc[8][4];
    #pragma unroll
    for (int c=0;c<8;c++)
      #pragma unroll
      for (int k=0;k<4;k++) acc[c][k]=0.f;

    for (int ch=0; ch<4; ch++){
        if (ch+1 < 4){
            #pragma unroll
            for (int j=0;j<8;j++){
                int s = tid + 128*j;
                int row = s>>3, seg = s&7;
                cpa16(&ts[(ch+1)&1][row][seg*8],
                      g_kvh + base + (size_t)row*Nn + (ch+1)*64 + seg*8);
            }
            CP_COMMIT(); CP_WAIT1();
        } else CP_WAIT0();
        __syncthreads();
        const int buf = ch&1;
        #pragma unroll
        for (int step=0; step<4; step++){
            int kl = step*16 + t4*2;
            unsigned af[4];
            int m = warp*16 + g;
            af[0] = ldh2(&ts[buf][m][kl]);
            af[1] = ldh2(&ts[buf][m+8][kl]);
            af[2] = ldh2(&ts[buf][m][kl+8]);
            af[3] = ldh2(&ts[buf][m+8][kl+8]);
            #pragma unroll
            for (int n8=0;n8<8;n8++){
                int e = n8*8 + g;
                unsigned bf[2];
                bf[0] = ldh2(&ts[buf][64+e][kl]);
                bf[1] = ldh2(&ts[buf][64+e][kl+8]);
                mma16h(acc[n8], af, bf);
            }
        }
        __syncthreads();
    }
    float* outp = g_ctx_part + ((size_t)b*16 + sp)*KD*KD;
    #pragma unroll
    for (int n8=0;n8<8;n8++){
        int r0 = warp*16 + g;
        int c  = n8*8 + 2*t4;
        *(float2*)(outp + r0*KD + c)     = make_float2(acc[n8][0], acc[n8][1]);
        *(float2*)(outp + (r0+8)*KD + c) = make_float2(acc[n8][2], acc[n8][3]);
    }
}

// ---------------- K3b: reduce partials, divide by rowsum ----------------
__global__ void __launch_bounds__(256) ctx_reduce_kernel()
{
    int b = blockIdx.x, tid = threadIdx.x;
    for (int i = tid; i < KD*KD; i += 256) {
        int d = i >> 6;
        float s = 0.f;
        #pragma unroll
        for (int p = 0; p < 16; p++) s += g_ctx_part[((size_t)b*16+p)*KD*KD + i];
        g_ctx[(size_t)b*KD*KD + i] = s / g_rowsum[b*KD + d];
    }
}

// ---------------- K4: M = Wo folded with ctx -> half ----------------
__global__ void __launch_bounds__(256) m_kernel(const float* __restrict__ Wo)
{
    __shared__ float WoS[64*65];
    __shared__ float cS[64*65];
    int h = blockIdx.x, ot = blockIdx.y, b = blockIdx.z;
    int tid = threadIdx.x;
    int ty = tid >> 4, tx = tid & 15;
    for (int i = tid; i < 64*64; i += 256) {
        int r = i >> 6, e = i & 63;
        WoS[r*65+e] = Wo[(ot*64 + r)*QD + h*64 + e];
        cS[r*65+e]  = g_ctx[(size_t)b*KD*KD + r*64 + e];
    }
    __syncthreads();
    float acc[4][4] = {};
    #pragma unroll
    for (int e = 0; e < 64; e++) {
        float a[4], bb[4];
        #pragma unroll
        for (int i=0;i<4;i++) a[i] = WoS[(ty*4+i)*65+e];
        #pragma unroll
        for (int j=0;j<4;j++) bb[j] = cS[(tx*4+j)*65+e];
        #pragma unroll
        for (int i=0;i<4;i++)
            #pragma unroll
            for (int j=0;j<4;j++) acc[i][j] += a[i]*bb[j];
    }
    #pragma unroll
    for (int i=0;i<4;i++)
        #pragma unroll
        for (int j=0;j<4;j++)
            g_Mh[((size_t)b*OD + ot*64 + ty*4+i)*QD + h*64 + tx*4+j] = __float2half_rn(acc[i][j]);
}

// ---------------- K5: fused q-proj(fp16) -> softmax(d) -> out GEMM (fp16) ----------------
// grid (64, 32), 256 thr.
// smem: region0 = max(xs half[64][264], qs half[64][520]) = 66560 B
//       region1 = As half[2][512][40] = 81920 B  (phase C reuses as Msh [2][256][40])
// total = 148480 B
__global__ void __launch_bounds__(256) fused_q_out_mma(
    const float* __restrict__ x, const float* __restrict__ bq,
    const float* __restrict__ bo, float* __restrict__ out)
{
    extern __shared__ __half smh[];
    __half* xs  = smh;                  // [64][264] (phase A, transposed x)
    __half* qs  = smh;                  // [64][520] (phase B/C), aliases xs region
    __half* As  = smh + 33280;          // [2][512][40] phase A; [2][256][40] phase C
    const int nt = blockIdx.x, b = blockIdx.y;
    const int n0 = nt*64;
    const int tid = threadIdx.x;
    const int warp = tid>>5, lane = tid&31;
    const int g = lane>>2, t4 = lane&3;

    // x tile [256 c][64 n] -> xs[n][c] as half
    for (int i = tid; i < 256*16; i += 256) {
        int c = i>>4, n4 = (i&15)*4;
        float4 val = *(const float4*)(x + ((size_t)b*Cc + c)*Nn + n0 + n4);
        xs[(n4+0)*264 + c] = __float2half_rn(val.x);
        xs[(n4+1)*264 + c] = __float2half_rn(val.y);
        xs[(n4+2)*264 + c] = __float2half_rn(val.z);
        xs[(n4+3)*264 + c] = __float2half_rn(val.w);
    }
    // prefetch Wq chunk 0 (512 rows x 32 halves)
    #pragma unroll
    for (int j=0;j<8;j++){
        int s = tid + 256*j;             // 0..2047
        int row = s>>2, seg = s&3;
        cpa16(As + row*40 + seg*8, g_Wqh + row*Cc + seg*8);
    }
    CP_COMMIT();

    // ---- Phase A (fp16): q = Wq @ x ; warp == head, warp tile 64x64 ----
    float acc[4][8][4];
    #pragma unroll
    for (int a=0;a<4;a++)
      #pragma unroll
      for (int c=0;c<8;c++)
        #pragma unroll
        for (int k=0;k<4;k++) acc[a][c][k]=0.f;

    const int NKA = 8;    // 256 / 32
    for (int kc=0; kc<NKA; kc++){
        if (kc+1 < NKA){
            __half* dst = As + ((kc+1)&1)*20480;
            const __half* src = g_Wqh + (kc+1)*32;
            #pragma unroll
            for (int j=0;j<8;j++){
                int s = tid + 256*j;
                int row = s>>2, seg = s&3;
                cpa16(dst + row*40 + seg*8, src + row*Cc + seg*8);
            }
            CP_COMMIT(); CP_WAIT1();
        } else CP_WAIT0();
        __syncthreads();
        const __half* A0 = As + (kc&1)*20480 + (warp*64)*40;
        #pragma unroll
        for (int sub=0; sub<2; sub++){
            int kl = sub*16 + t4*2;
            int kabs = kc*32 + kl;
            unsigned bf[8][2];
            #pragma unroll
            for (int n8=0;n8<8;n8++){
                int n = n8*8 + g;
                bf[n8][0] = ldh2(xs + n*264 + kabs);
                bf[n8][1] = ldh2(xs + n*264 + kabs + 8);
            }
            #pragma unroll
            for (int mt=0;mt<4;mt++){
                const __half* Ap = A0 + (mt*16 + g)*40 + kl;
                unsigned af[4];
                af[0] = ldh2(Ap);
                af[1] = ldh2(Ap + 8*40);
                af[2] = ldh2(Ap + 8);
                af[3] = ldh2(Ap + 8*40 + 8);
                #pragma unroll
                for (int n8=0;n8<8;n8++) mma16h(acc[mt][n8], af, bf[n8]);
            }
        }
        __syncthreads();
    }

    // ---- Phase B: bias + exp + softmax over kd (this warp = one head) ----
    #pragma unroll
    for (int mt=0;mt<4;mt++){
        float b0 = bq[warp*64 + mt*16 + g];
        float b1 = bq[warp*64 + mt*16 + g + 8];
        #pragma unroll
        for (int n8=0;n8<8;n8++){
            acc[mt][n8][0] = __expf(acc[mt][n8][0] + b0);
            acc[mt][n8][1] = __expf(acc[mt][n8][1] + b0);
            acc[mt][n8][2] = __expf(acc[mt][n8][2] + b1);
            acc[mt][n8][3] = __expf(acc[mt][n8][3] + b1);
        }
    }
    float inv[8][2];
    #pragma unroll
    for (int n8=0;n8<8;n8++){
        #pragma unroll
        for (int p=0;p<2;p++){
            float s = 0.f;
            #pragma unroll
            for (int mt=0;mt<4;mt++) s += acc[mt][n8][p] + acc[mt][n8][p+2];
            s += __shfl_xor_sync(0xffffffffu, s, 4);
            s += __shfl_xor_sync(0xffffffffu, s, 8);
            s += __shfl_xor_sync(0xffffffffu, s, 16);
            inv[n8][p] = 1.f/s;
        }
    }
    __syncthreads();   // all warps done reading xs & As
    // write q_s transposed into qs[n][k] as half
    #pragma unroll
    for (int mt=0;mt<4;mt++){
        int k0 = warp*64 + mt*16 + g;
        #pragma unroll
        for (int n8=0;n8<8;n8++){
            int n = n8*8 + 2*t4;
            qs[n*520 + k0]       = __float2half_rn(acc[mt][n8][0]*inv[n8][0]);
            qs[(n+1)*520 + k0]   = __float2half_rn(acc[mt][n8][1]*inv[n8][1]);
            qs[n*520 + k0+8]     = __float2half_rn(acc[mt][n8][2]*inv[n8][0]);
            qs[(n+1)*520 + k0+8] = __float2half_rn(acc[mt][n8][3]*inv[n8][1]);
        }
    }
    __syncthreads();

    // ---- Phase C (fp16): out = M[b] @ qs ; M is 256 rows x 512 cols ----
    const __half* Mb = g_Mh + (size_t)b*OD*QD;
    __half* Msh = As;                   // [2][256][40]
    // stage k-chunk 0: 256 rows x 32 halves
    #pragma unroll
    for (int j=0;j<4;j++){
        int s = tid + 256*j;            // 0..1023
        int row = s>>2, seg = s&3;
        cpa16(Msh + row*40 + seg*8, Mb + row*QD + seg*8);
    }
    CP_COMMIT();

    float acc2[4][4][4];
    #pragma unroll
    for (int a=0;a<4;a++)
      #pragma unroll
      for (int c=0;c<4;c++)
        #pragma unroll
        for (int k=0;k<4;k++) acc2[a][c][k]=0.f;

    const int wr = warp>>1, wc = warp&1;
    const int NKC = 16;                  // 512 / 32
    for (int ki=0; ki<NKC; ki++){
        if (ki+1 < NKC){
            __half* dst = Msh + ((ki+1)&1)*10240;
            const __half* src = Mb + (ki+1)*32;
            #pragma unroll
            for (int j=0;j<4;j++){
                int s = tid + 256*j;
                int row = s>>2, seg = s&3;
                cpa16(dst + row*40 + seg*8, src + row*QD + seg*8);
            }
            CP_COMMIT(); CP_WAIT1();
        } else CP_WAIT0();
        __syncthreads();
        const __half* A0 = Msh + (ki&1)*10240 + (wr*64)*40;
        #pragma unroll
        for (int sub=0; sub<2; sub++){
            int kl = sub*16 + t4*2;
            int kabs = ki*32 + kl;
            unsigned bf[4][2];
            #pragma unroll
            for (int n8=0;n8<4;n8++){
                int n = wc*32 + n8*8 + g;
                bf[n8][0] = ldh2(qs + n*520 + kabs);
                bf[n8][1] = ldh2(qs + n*520 + kabs + 8);
            }
            #pragma unroll
            for (int mt=0;mt<4;mt++){
                const __half* Ap = A0 + (mt*16 + g)*40 + kl;
                unsigned af[4];
                af[0] = ldh2(Ap);
                af[1] = ldh2(Ap + 8*40);
                af[2] = ldh2(Ap + 8);
                af[3] = ldh2(Ap + 8*40 + 8);
                #pragma unroll
                for (int n8=0;n8<4;n8++) mma16h(acc2[mt][n8], af, bf[n8]);
            }
        }
        __syncthreads();
    }
    // epilogue
    #pragma unroll
    for (int mt=0;mt<4;mt++){
        int r0 = wr*64 + mt*16 + g;
        float bo0 = bo[r0], bo1 = bo[r0+8];
        #pragma unroll
        for (int n8=0;n8<4;n8++){
            int c = n0 + wc*32 + n8*8 + 2*t4;
            *(float2*)(out + ((size_t)b*OD + r0)*Nn + c) =
                make_float2(acc2[mt][n8][0]+bo0, acc2[mt][n8][1]+bo0);
            *(float2*)(out + ((size_t)b*OD + r0+8)*Nn + c) =
                make_float2(acc2[mt][n8][2]+bo1, acc2[mt][n8][3]+bo1);
        }
    }
}

// ---------------- launch ----------------
extern "C" void kernel_launch(void* const* d_in, const int* in_sizes, int n_in,
                              void* d_out, int out_size)
{
    const float* x  = (const float*)d_in[0];
    const float* Wq = (const float*)d_in[1];
    const float* bq = (const float*)d_in[2];
    const float* Wk = (const float*)d_in[3];
    const float* bk = (const float*)d_in[4];
    const float* Wv = (const float*)d_in[5];
    const float* bv = (const float*)d_in[6];
    const float* Wo = (const float*)d_in[7];
    const float* bo = (const float*)d_in[8];
    float* out = (float*)d_out;

    round_kernel<<<512, 256>>>(Wq, Wk, Wv);

    cudaFuncSetAttribute(kv_proj_h, cudaFuncAttributeMaxDynamicSharedMemorySize, 54272);
    kv_proj_h<<<dim3(64,32), 256, 54272>>>(x, bk, bv);

    rowsum_kernel<<<dim3(64,32), 256>>>();
    ctx_part_h<<<dim3(16,32), 128>>>();
    ctx_reduce_kernel<<<32, 256>>>();
    m_kernel<<<dim3(8,4,32), 256>>>(Wo);

    cudaFuncSetAttribute(fused_q_out_mma, cudaFuncAttributeMaxDynamicSharedMemorySize, 148480);
    fused_q_out_mma<<<dim3(64,32), 256, 148480>>>(x, bq, bo, out);
}

// round 13
// speedup vs baseline: 1.0018x; 1.0018x over previous
#include <cuda_runtime.h>
#include <cuda_fp16.h>
#include <math.h>

#define Bb 32
#define Cc 256
#define Nn 4096
#define KD 64
#define HEADS 8
#define QD 512
#define OD 256

// ---------------- scratch (device globals; allocation-free) ----------------
__device__ __align__(256) __half g_kvh[(size_t)Bb*128*Nn];   // rows 0..63 exp(k), 64..127 v (half)
__device__ __align__(256) float  g_rowsum[Bb*KD];
__device__ __align__(256) float  g_ctx_part[(size_t)Bb*16*KD*KD];
__device__ __align__(256) float  g_ctx[(size_t)Bb*KD*KD];
__device__ __align__(256) __half g_Mh[(size_t)Bb*OD*QD];     // folded Wo*ctx, half
__device__ __align__(256) __half g_Wqh[QD*Cc];               // half Wq
__device__ __align__(256) __half g_Wkvh[128*Cc];             // half [Wk; Wv]

// ---------------- helpers ----------------
__device__ __forceinline__ void mma16h(float* d, const unsigned* a, const unsigned* b){
    asm volatile("mma.sync.aligned.m16n8k16.row.col.f32.f16.f16.f32 "
        "{%0,%1,%2,%3}, {%4,%5,%6,%7}, {%8,%9}, {%0,%1,%2,%3};"
        : "+f"(d[0]), "+f"(d[1]), "+f"(d[2]), "+f"(d[3])
        : "r"(a[0]), "r"(a[1]), "r"(a[2]), "r"(a[3]), "r"(b[0]), "r"(b[1]));
}
__device__ __forceinline__ void cpa16(void* smem_dst, const void* gsrc){
    unsigned s = (unsigned)__cvta_generic_to_shared(smem_dst);
    asm volatile("cp.async.cg.shared.global [%0], [%1], 16;" :: "r"(s), "l"(gsrc));
}
#define CP_COMMIT() asm volatile("cp.async.commit_group;")
#define CP_WAIT1()  asm volatile("cp.async.wait_group 1;")
#define CP_WAIT0()  asm volatile("cp.async.wait_group 0;")
__device__ __forceinline__ unsigned ldh2(const __half* p){ return *(const unsigned*)p; }

// ---------------- K0: convert weights to half, zero rowsum ----------------
__global__ void __launch_bounds__(256) round_kernel(
    const float* __restrict__ Wq, const float* __restrict__ Wk, const float* __restrict__ Wv)
{
    int i = blockIdx.x*256 + threadIdx.x;
    if (i < QD*Cc) g_Wqh[i] = __float2half_rn(Wq[i]);
    if (i < KD*Cc) { g_Wkvh[i] = __float2half_rn(Wk[i]); g_Wkvh[KD*Cc + i] = __float2half_rn(Wv[i]); }
    if (i < Bb*KD) g_rowsum[i] = 0.f;
}

// ---------------- K1: kv projection (fp16 MMA) -> exp(k), v (half), fused rowsum ----------------
// grid (32 ntiles of 128, 32 b), 256 thr. smem: xs half[128][264] + As half[2][128][40] = 88064 B
__global__ void __launch_bounds__(256) kv_proj_h(
    const float* __restrict__ x, const float* __restrict__ bk, const float* __restrict__ bv)
{
    extern __shared__ __half smk[];
    __half* xs = smk;                 // [n=128][c=264] (transposed, c contiguous)
    __half* As = smk + 128*264;       // [2][128][40]
    const int nt = blockIdx.x, b = blockIdx.y;
    const int n0 = nt*128;
    const int tid = threadIdx.x;
    const int warp = tid>>5, lane = tid&31;
    const int g = lane>>2, t4 = lane&3;
    const int wr = warp>>1, wc = warp&1;   // wr: 32-row group (0..3); wc: 64-col half (0..1)

    // load x tile [256 c][128 n], store transposed as half
    for (int i = tid; i < 256*32; i += 256) {
        int c = i>>5, n4 = (i&31)*4;
        float4 val = *(const float4*)(x + ((size_t)b*Cc + c)*Nn + n0 + n4);
        xs[(n4+0)*264 + c] = __float2half_rn(val.x);
        xs[(n4+1)*264 + c] = __float2half_rn(val.y);
        xs[(n4+2)*264 + c] = __float2half_rn(val.z);
        xs[(n4+3)*264 + c] = __float2half_rn(val.w);
    }
    // prefetch W chunk 0 (128 rows x 32 halves)
    #pragma unroll
    for (int j=0;j<2;j++){
        int s = tid + 256*j;             // 0..511
        int row = s>>2, seg = s&3;
        cpa16(As + row*40 + seg*8, g_Wkvh + row*Cc + seg*8);
    }
    CP_COMMIT();

    float acc[2][8][4];
    #pragma unroll
    for (int a=0;a<2;a++)
      #pragma unroll
      for (int c=0;c<8;c++)
        #pragma unroll
        for (int k=0;k<4;k++) acc[a][c][k]=0.f;

    const int NK = 8;   // 256 / 32
    for (int kc=0; kc<NK; kc++){
        if (kc+1 < NK){
            __half* dst = As + ((kc+1)&1)*5120;
            const __half* src = g_Wkvh + (kc+1)*32;
            #pragma unroll
            for (int j=0;j<2;j++){
                int s = tid + 256*j;
                int row = s>>2, seg = s&3;
                cpa16(dst + row*40 + seg*8, src + row*Cc + seg*8);
            }
            CP_COMMIT(); CP_WAIT1();
        } else CP_WAIT0();
        __syncthreads();
        const __half* A0 = As + (kc&1)*5120 + (wr*32)*40;
        #pragma unroll
        for (int sub=0; sub<2; sub++){
            int kl = sub*16 + t4*2;
            int kabs = kc*32 + kl;
            unsigned bf[8][2];
            #pragma unroll
            for (int n8=0;n8<8;n8++){
                int n = wc*64 + n8*8 + g;
                bf[n8][0] = ldh2(xs + n*264 + kabs);
                bf[n8][1] = ldh2(xs + n*264 + kabs + 8);
            }
            #pragma unroll
            for (int mt=0;mt<2;mt++){
                const __half* Ap = A0 + (mt*16 + g)*40 + kl;
                unsigned af[4];
                af[0] = ldh2(Ap);
                af[1] = ldh2(Ap + 8*40);
                af[2] = ldh2(Ap + 8);
                af[3] = ldh2(Ap + 8*40 + 8);
                #pragma unroll
                for (int n8=0;n8<8;n8++) mma16h(acc[mt][n8], af, bf[n8]);
            }
        }
        __syncthreads();
    }
    // epilogue: bias, exp for k-rows, store half2, fused rowsum for k-rows
    #pragma unroll
    for (int mt=0;mt<2;mt++){
        int r0 = wr*32 + mt*16 + g;
        int r1 = r0 + 8;
        bool isk = (r0 < 64);
        float bi0 = isk ? bk[r0] : bv[r0-64];
        float bi1 = isk ? bk[r1] : bv[r1-64];
        float s0 = 0.f, s1 = 0.f;
        #pragma unroll
        for (int n8=0;n8<8;n8++){
            int c = n0 + wc*64 + n8*8 + 2*t4;
            float v00 = acc[mt][n8][0]+bi0, v01 = acc[mt][n8][1]+bi0;
            float v10 = acc[mt][n8][2]+bi1, v11 = acc[mt][n8][3]+bi1;
            if (isk){ v00=__expf(v00); v01=__expf(v01); v10=__expf(v10); v11=__expf(v11); }
            __half2 h0 = __floats2half2_rn(v00, v01);
            __half2 h1 = __floats2half2_rn(v10, v11);
            *(__half2*)(g_kvh + ((size_t)b*128 + r0)*Nn + c) = h0;
            *(__half2*)(g_kvh + ((size_t)b*128 + r1)*Nn + c) = h1;
            if (isk){
                s0 += __low2float(h0) + __high2float(h0);
                s1 += __low2float(h1) + __high2float(h1);
            }
        }
        if (isk){
            s0 += __shfl_xor_sync(0xffffffffu, s0, 1);
            s0 += __shfl_xor_sync(0xffffffffu, s0, 2);
            s1 += __shfl_xor_sync(0xffffffffu, s1, 1);
            s1 += __shfl_xor_sync(0xffffffffu, s1, 2);
            if (t4 == 0){
                atomicAdd(&g_rowsum[b*KD + r0], s0);
                atomicAdd(&g_rowsum[b*KD + r1], s1);
            }
        }
    }
}

// ---------------- K3a: ctx partials via fp16 MMA ----------------
__global__ void __launch_bounds__(128) ctx_part_h()
{
    __shared__ __align__(16) __half ts[2][128][72];
    const int sp = blockIdx.x, b = blockIdx.y;
    const int tid = threadIdx.x;
    const int warp = tid>>5, lane = tid&31;
    const int g = lane>>2, t4 = lane&3;
    const size_t base = (size_t)b*128*Nn + sp*256;

    #pragma unroll
    for (int j=0;j<8;j++){
        int s = tid + 128*j;
        int row = s>>3, seg = s&7;
        cpa16(&ts[0][row][seg*8], g_kvh + base + (size_t)row*Nn + seg*8);
    }
    CP_COMMIT();

    float acc[8][4];
    #pragma unroll
    for (int c=0;c<8;c++)
      #pragma unroll
      for (int k=0;k<4;k++) acc[c][k]=0.f;

    for (int ch=0; ch<4; ch++){
        if (ch+1 < 4){
            #pragma unroll
            for (int j=0;j<8;j++){
                int s = tid + 128*j;
                int row = s>>3, seg = s&7;
                cpa16(&ts[(ch+1)&1][row][seg*8],
                      g_kvh + base + (size_t)row*Nn + (ch+1)*64 + seg*8);
            }
            CP_COMMIT(); CP_WAIT1();
        } else CP_WAIT0();
        __syncthreads();
        const int buf = ch&1;
        #pragma unroll
        for (int step=0; step<4; step++){
            int kl = step*16 + t4*2;
            unsigned af[4];
            int m = warp*16 + g;
            af[0] = ldh2(&ts[buf][m][kl]);
            af[1] = ldh2(&ts[buf][m+8][kl]);
            af[2] = ldh2(&ts[buf][m][kl+8]);
            af[3] = ldh2(&ts[buf][m+8][kl+8]);
            #pragma unroll
            for (int n8=0;n8<8;n8++){
                int e = n8*8 + g;
                unsigned bf[2];
                bf[0] = ldh2(&ts[buf][64+e][kl]);
                bf[1] = ldh2(&ts[buf][64+e][kl+8]);
                mma16h(acc[n8], af, bf);
            }
        }
        __syncthreads();
    }
    float* outp = g_ctx_part + ((size_t)b*16 + sp)*KD*KD;
    #pragma unroll
    for (int n8=0;n8<8;n8++){
        int r0 = warp*16 + g;
        int c  = n8*8 + 2*t4;
        *(float2*)(outp + r0*KD + c)     = make_float2(acc[n8][0], acc[n8][1]);
        *(float2*)(outp + (r0+8)*KD + c) = make_float2(acc[n8][2], acc[n8][3]);
    }
}

// ---------------- K3b: reduce partials, divide by rowsum ----------------
__global__ void __launch_bounds__(256) ctx_reduce_kernel()
{
    int b = blockIdx.x, tid = threadIdx.x;
    for (int i = tid; i < KD*KD; i += 256) {
        int d = i >> 6;
        float s = 0.f;
        #pragma unroll
        for (int p = 0; p < 16; p++) s += g_ctx_part[((size_t)b*16+p)*KD*KD + i];
        g_ctx[(size_t)b*KD*KD + i] = s / g_rowsum[b*KD + d];
    }
}

// ---------------- K4: M = Wo folded with ctx -> half ----------------
__global__ void __launch_bounds__(256) m_kernel(const float* __restrict__ Wo)
{
    __shared__ float WoS[64*65];
    __shared__ float cS[64*65];
    int h = blockIdx.x, ot = blockIdx.y, b = blockIdx.z;
    int tid = threadIdx.x;
    int ty = tid >> 4, tx = tid & 15;
    for (int i = tid; i < 64*64; i += 256) {
        int r = i >> 6, e = i & 63;
        WoS[r*65+e] = Wo[(ot*64 + r)*QD + h*64 + e];
        cS[r*65+e]  = g_ctx[(size_t)b*KD*KD + r*64 + e];
    }
    __syncthreads();
    float acc[4][4] = {};
    #pragma unroll
    for (int e = 0; e < 64; e++) {
        float a[4], bb[4];
        #pragma unroll
        for (int i=0;i<4;i++) a[i] = WoS[(ty*4+i)*65+e];
        #pragma unroll
        for (int j=0;j<4;j++) bb[j] = cS[(tx*4+j)*65+e];
        #pragma unroll
        for (int i=0;i<4;i++)
            #pragma unroll
            for (int j=0;j<4;j++) acc[i][j] += a[i]*bb[j];
    }
    #pragma unroll
    for (int i=0;i<4;i++)
        #pragma unroll
        for (int j=0;j<4;j++)
            g_Mh[((size_t)b*OD + ot*64 + ty*4+i)*QD + h*64 + tx*4+j] = __float2half_rn(acc[i][j]);
}

// ---------------- K5: fused q-proj(fp16) -> softmax(d) -> out GEMM (fp16) ----------------
// grid (64, 32), 256 thr.
// smem: region0 = max(xs half[64][264], qs half[64][520]) = 66560 B
//       region1 = As half[2][512][40] = 81920 B  (phase C reuses as Msh [2][256][40])
// total = 148480 B
__global__ void __launch_bounds__(256) fused_q_out_mma(
    const float* __restrict__ x, const float* __restrict__ bq,
    const float* __restrict__ bo, float* __restrict__ out)
{
    extern __shared__ __half smh[];
    __half* xs  = smh;                  // [64][264] (phase A, transposed x)
    __half* qs  = smh;                  // [64][520] (phase B/C), aliases xs region
    __half* As  = smh + 33280;          // [2][512][40] phase A; [2][256][40] phase C
    const int nt = blockIdx.x, b = blockIdx.y;
    const int n0 = nt*64;
    const int tid = threadIdx.x;
    const int warp = tid>>5, lane = tid&31;
    const int g = lane>>2, t4 = lane&3;

    // x tile [256 c][64 n] -> xs[n][c] as half
    for (int i = tid; i < 256*16; i += 256) {
        int c = i>>4, n4 = (i&15)*4;
        float4 val = *(const float4*)(x + ((size_t)b*Cc + c)*Nn + n0 + n4);
        xs[(n4+0)*264 + c] = __float2half_rn(val.x);
        xs[(n4+1)*264 + c] = __float2half_rn(val.y);
        xs[(n4+2)*264 + c] = __float2half_rn(val.z);
        xs[(n4+3)*264 + c] = __float2half_rn(val.w);
    }
    // prefetch Wq chunk 0 (512 rows x 32 halves)
    #pragma unroll
    for (int j=0;j<8;j++){
        int s = tid + 256*j;             // 0..2047
        int row = s>>2, seg = s&3;
        cpa16(As + row*40 + seg*8, g_Wqh + row*Cc + seg*8);
    }
    CP_COMMIT();

    // ---- Phase A (fp16): q = Wq @ x ; warp == head, warp tile 64x64 ----
    float acc[4][8][4];
    #pragma unroll
    for (int a=0;a<4;a++)
      #pragma unroll
      for (int c=0;c<8;c++)
        #pragma unroll
        for (int k=0;k<4;k++) acc[a][c][k]=0.f;

    const int NKA = 8;    // 256 / 32
    for (int kc=0; kc<NKA; kc++){
        if (kc+1 < NKA){
            __half* dst = As + ((kc+1)&1)*20480;
            const __half* src = g_Wqh + (kc+1)*32;
            #pragma unroll
            for (int j=0;j<8;j++){
                int s = tid + 256*j;
                int row = s>>2, seg = s&3;
                cpa16(dst + row*40 + seg*8, src + row*Cc + seg*8);
            }
            CP_COMMIT(); CP_WAIT1();
        } else CP_WAIT0();
        __syncthreads();
        const __half* A0 = As + (kc&1)*20480 + (warp*64)*40;
        #pragma unroll
        for (int sub=0; sub<2; sub++){
            int kl = sub*16 + t4*2;
            int kabs = kc*32 + kl;
            unsigned bf[8][2];
            #pragma unroll
            for (int n8=0;n8<8;n8++){
                int n = n8*8 + g;
                bf[n8][0] = ldh2(xs + n*264 + kabs);
                bf[n8][1] = ldh2(xs + n*264 + kabs + 8);
            }
            #pragma unroll
            for (int mt=0;mt<4;mt++){
                const __half* Ap = A0 + (mt*16 + g)*40 + kl;
                unsigned af[4];
                af[0] = ldh2(Ap);
                af[1] = ldh2(Ap + 8*40);
                af[2] = ldh2(Ap + 8);
                af[3] = ldh2(Ap + 8*40 + 8);
                #pragma unroll
                for (int n8=0;n8<8;n8++) mma16h(acc[mt][n8], af, bf[n8]);
            }
        }
        __syncthreads();
    }

    // ---- prefetch M chunks 0,1 into Msh (As region is dead now); overlaps softmax ----
    const __half* Mb = g_Mh + (size_t)b*OD*QD;
    __half* Msh = As;                   // [2][256][40]
    #pragma unroll
    for (int j=0;j<4;j++){
        int s = tid + 256*j;            // 0..1023
        int row = s>>2, seg = s&3;
        cpa16(Msh + row*40 + seg*8, Mb + row*QD + seg*8);
    }
    CP_COMMIT();
    #pragma unroll
    for (int j=0;j<4;j++){
        int s = tid + 256*j;
        int row = s>>2, seg = s&3;
        cpa16(Msh + 10240 + row*40 + seg*8, Mb + 32 + row*QD + seg*8);
    }
    CP_COMMIT();

    // ---- Phase B: bias + exp + softmax over kd (this warp = one head) ----
    #pragma unroll
    for (int mt=0;mt<4;mt++){
        float b0 = bq[warp*64 + mt*16 + g];
        float b1 = bq[warp*64 + mt*16 + g + 8];
        #pragma unroll
        for (int n8=0;n8<8;n8++){
            acc[mt][n8][0] = __expf(acc[mt][n8][0] + b0);
            acc[mt][n8][1] = __expf(acc[mt][n8][1] + b0);
            acc[mt][n8][2] = __expf(acc[mt][n8][2] + b1);
            acc[mt][n8][3] = __expf(acc[mt][n8][3] + b1);
        }
    }
    float inv[8][2];
    #pragma unroll
    for (int n8=0;n8<8;n8++){
        #pragma unroll
        for (int p=0;p<2;p++){
            float s = 0.f;
            #pragma unroll
            for (int mt=0;mt<4;mt++) s += acc[mt][n8][p] + acc[mt][n8][p+2];
            s += __shfl_xor_sync(0xffffffffu, s, 4);
            s += __shfl_xor_sync(0xffffffffu, s, 8);
            s += __shfl_xor_sync(0xffffffffu, s, 16);
            inv[n8][p] = 1.f/s;
        }
    }
    // write q_s transposed into qs[n][k] as half (xs reads all completed before
    // the final phase-A __syncthreads, so the alias is safe)
    #pragma unroll
    for (int mt=0;mt<4;mt++){
        int k0 = warp*64 + mt*16 + g;
        #pragma unroll
        for (int n8=0;n8<8;n8++){
            int n = n8*8 + 2*t4;
            qs[n*520 + k0]       = __float2half_rn(acc[mt][n8][0]*inv[n8][0]);
            qs[(n+1)*520 + k0]   = __float2half_rn(acc[mt][n8][1]*inv[n8][1]);
            qs[n*520 + k0+8]     = __float2half_rn(acc[mt][n8][2]*inv[n8][0]);
            qs[(n+1)*520 + k0+8] = __float2half_rn(acc[mt][n8][3]*inv[n8][1]);
        }
    }
    __syncthreads();

    // ---- Phase C (fp16): out = M[b] @ qs ; M is 256 rows x 512 cols ----
    float acc2[4][4][4];
    #pragma unroll
    for (int a=0;a<4;a++)
      #pragma unroll
      for (int c=0;c<4;c++)
        #pragma unroll
        for (int k=0;k<4;k++) acc2[a][c][k]=0.f;

    const int wr = warp>>1, wc = warp&1;
    const int NKC = 16;                  // 512 / 32
    for (int ki=0; ki<NKC; ki++){
        if (ki < NKC-1) CP_WAIT1(); else CP_WAIT0();
        __syncthreads();
        const __half* A0 = Msh + (ki&1)*10240 + (wr*64)*40;
        #pragma unroll
        for (int sub=0; sub<2; sub++){
            int kl = sub*16 + t4*2;
            int kabs = ki*32 + kl;
            unsigned bf[4][2];
            #pragma unroll
            for (int n8=0;n8<4;n8++){
                int n = wc*32 + n8*8 + g;
                bf[n8][0] = ldh2(qs + n*520 + kabs);
                bf[n8][1] = ldh2(qs + n*520 + kabs + 8);
            }
            #pragma unroll
            for (int mt=0;mt<4;mt++){
                const __half* Ap = A0 + (mt*16 + g)*40 + kl;
                unsigned af[4];
                af[0] = ldh2(Ap);
                af[1] = ldh2(Ap + 8*40);
                af[2] = ldh2(Ap + 8);
                af[3] = ldh2(Ap + 8*40 + 8);
                #pragma unroll
                for (int n8=0;n8<4;n8++) mma16h(acc2[mt][n8], af, bf[n8]);
            }
        }
        __syncthreads();
        if (ki + 2 < NKC){
            __half* dst = Msh + (ki&1)*10240;
            const __half* src = Mb + (ki+2)*32;
            #pragma unroll
            for (int j=0;j<4;j++){
                int s = tid + 256*j;
                int row = s>>2, seg = s&3;
                cpa16(dst + row*40 + seg*8, src + row*QD + seg*8);
            }
            CP_COMMIT();
        }
    }
    // epilogue
    #pragma unroll
    for (int mt=0;mt<4;mt++){
        int r0 = wr*64 + mt*16 + g;
        float bo0 = bo[r0], bo1 = bo[r0+8];
        #pragma unroll
        for (int n8=0;n8<4;n8++){
            int c = n0 + wc*32 + n8*8 + 2*t4;
            *(float2*)(out + ((size_t)b*OD + r0)*Nn + c) =
                make_float2(acc2[mt][n8][0]+bo0, acc2[mt][n8][1]+bo0);
            *(float2*)(out + ((size_t)b*OD + r0+8)*Nn + c) =
                make_float2(acc2[mt][n8][2]+bo1, acc2[mt][n8][3]+bo1);
        }
    }
}

// ---------------- launch ----------------
extern "C" void kernel_launch(void* const* d_in, const int* in_sizes, int n_in,
                              void* d_out, int out_size)
{
    const float* x  = (const float*)d_in[0];
    const float* Wq = (const float*)d_in[1];
    const float* bq = (const float*)d_in[2];
    const float* Wk = (const float*)d_in[3];
    const float* bk = (const float*)d_in[4];
    const float* Wv = (const float*)d_in[5];
    const float* bv = (const float*)d_in[6];
    const float* Wo = (const float*)d_in[7];
    const float* bo = (const float*)d_in[8];
    float* out = (float*)d_out;

    round_kernel<<<512, 256>>>(Wq, Wk, Wv);

    cudaFuncSetAttribute(kv_proj_h, cudaFuncAttributeMaxDynamicSharedMemorySize, 88064);
    kv_proj_h<<<dim3(32,32), 256, 88064>>>(x, bk, bv);

    ctx_part_h<<<dim3(16,32), 128>>>();
    ctx_reduce_kernel<<<32, 256>>>();
    m_kernel<<<dim3(8,4,32), 256>>>(Wo);

    cudaFuncSetAttribute(fused_q_out_mma, cudaFuncAttributeMaxDynamicSharedMemorySize, 148480);
    fused_q_out_mma<<<dim3(64,32), 256, 148480>>>(x, bq, bo, out);
}

// round 14
// speedup vs baseline: 1.0242x; 1.0223x over previous
#include <cuda_runtime.h>
#include <cuda_fp16.h>
#include <math.h>

#define Bb 32
#define Cc 256
#define Nn 4096
#define KD 64
#define HEADS 8
#define QD 512
#define OD 256

// ---------------- scratch (device globals; allocation-free) ----------------
__device__ __align__(256) float  g_rowsum[Bb*KD];
__device__ __align__(256) float  g_ctx_part[(size_t)Bb*32*KD*KD];  // 32 n-splits per batch
__device__ __align__(256) float  g_ctx[(size_t)Bb*KD*KD];
__device__ __align__(256) __half g_Mh[(size_t)Bb*OD*QD];     // folded Wo*ctx, half
__device__ __align__(256) __half g_Wqh[QD*Cc];               // half Wq
__device__ __align__(256) __half g_Wkvh[128*Cc];             // half [Wk; Wv]

// ---------------- helpers ----------------
__device__ __forceinline__ void mma16h(float* d, const unsigned* a, const unsigned* b){
    asm volatile("mma.sync.aligned.m16n8k16.row.col.f32.f16.f16.f32 "
        "{%0,%1,%2,%3}, {%4,%5,%6,%7}, {%8,%9}, {%0,%1,%2,%3};"
        : "+f"(d[0]), "+f"(d[1]), "+f"(d[2]), "+f"(d[3])
        : "r"(a[0]), "r"(a[1]), "r"(a[2]), "r"(a[3]), "r"(b[0]), "r"(b[1]));
}
__device__ __forceinline__ void cpa16(void* smem_dst, const void* gsrc){
    unsigned s = (unsigned)__cvta_generic_to_shared(smem_dst);
    asm volatile("cp.async.cg.shared.global [%0], [%1], 16;" :: "r"(s), "l"(gsrc));
}
#define CP_COMMIT() asm volatile("cp.async.commit_group;")
#define CP_WAIT1()  asm volatile("cp.async.wait_group 1;")
#define CP_WAIT0()  asm volatile("cp.async.wait_group 0;")
__device__ __forceinline__ unsigned ldh2(const __half* p){ return *(const unsigned*)p; }

// ---------------- K0: convert weights to half, zero rowsum ----------------
__global__ void __launch_bounds__(256) round_kernel(
    const float* __restrict__ Wq, const float* __restrict__ Wk, const float* __restrict__ Wv)
{
    int i = blockIdx.x*256 + threadIdx.x;
    if (i < QD*Cc) g_Wqh[i] = __float2half_rn(Wq[i]);
    if (i < KD*Cc) { g_Wkvh[i] = __float2half_rn(Wk[i]); g_Wkvh[KD*Cc + i] = __float2half_rn(Wv[i]); }
    if (i < Bb*KD) g_rowsum[i] = 0.f;
}

// ---------------- K1: fused kv projection + exp + rowsum + local ctx partial ----------------
// grid (32 ntiles of 128, 32 b), 256 thr. smem: xs half[128][264] + As half[2][128][40] = 88064 B
// epilogue keeps exp(k) (64x128) and v (64x128) in smem (reusing xs region) and
// computes this block's 64x64 ctx partial with fp16 MMA -> g_ctx_part[b*32+nt].
// NO k/v HBM round-trip.
__global__ void __launch_bounds__(256) kv_proj_ctx(
    const float* __restrict__ x, const float* __restrict__ bk, const float* __restrict__ bv)
{
    extern __shared__ __half smk[];
    __half* xs = smk;                 // [n=128][c=264] (phase 1)
    __half* kes = smk;                // [64][136] exp(k)  (phase 2, aliases xs)
    __half* vsb = smk + 64*136;       // [64][136] v       (phase 2)
    __half* As = smk + 128*264;       // [2][128][40] W staging
    const int nt = blockIdx.x, b = blockIdx.y;
    const int n0 = nt*128;
    const int tid = threadIdx.x;
    const int warp = tid>>5, lane = tid&31;
    const int g = lane>>2, t4 = lane&3;
    const int wr = warp>>1, wc = warp&1;   // wr: 32-row group (0..3); wc: 64-col half (0..1)

    // load x tile [256 c][128 n], store transposed as half
    for (int i = tid; i < 256*32; i += 256) {
        int c = i>>5, n4 = (i&31)*4;
        float4 val = *(const float4*)(x + ((size_t)b*Cc + c)*Nn + n0 + n4);
        xs[(n4+0)*264 + c] = __float2half_rn(val.x);
        xs[(n4+1)*264 + c] = __float2half_rn(val.y);
        xs[(n4+2)*264 + c] = __float2half_rn(val.z);
        xs[(n4+3)*264 + c] = __float2half_rn(val.w);
    }
    // prefetch W chunk 0 (128 rows x 32 halves)
    #pragma unroll
    for (int j=0;j<2;j++){
        int s = tid + 256*j;
        int row = s>>2, seg = s&3;
        cpa16(As + row*40 + seg*8, g_Wkvh + row*Cc + seg*8);
    }
    CP_COMMIT();

    float acc[2][8][4];
    #pragma unroll
    for (int a=0;a<2;a++)
      #pragma unroll
      for (int c=0;c<8;c++)
        #pragma unroll
        for (int k=0;k<4;k++) acc[a][c][k]=0.f;

    const int NK = 8;   // 256 / 32
    for (int kc=0; kc<NK; kc++){
        if (kc+1 < NK){
            __half* dst = As + ((kc+1)&1)*5120;
            const __half* src = g_Wkvh + (kc+1)*32;
            #pragma unroll
            for (int j=0;j<2;j++){
                int s = tid + 256*j;
                int row = s>>2, seg = s&3;
                cpa16(dst + row*40 + seg*8, src + row*Cc + seg*8);
            }
            CP_COMMIT(); CP_WAIT1();
        } else CP_WAIT0();
        __syncthreads();
        const __half* A0 = As + (kc&1)*5120 + (wr*32)*40;
        #pragma unroll
        for (int sub=0; sub<2; sub++){
            int kl = sub*16 + t4*2;
            int kabs = kc*32 + kl;
            unsigned bf[8][2];
            #pragma unroll
            for (int n8=0;n8<8;n8++){
                int n = wc*64 + n8*8 + g;
                bf[n8][0] = ldh2(xs + n*264 + kabs);
                bf[n8][1] = ldh2(xs + n*264 + kabs + 8);
            }
            #pragma unroll
            for (int mt=0;mt<2;mt++){
                const __half* Ap = A0 + (mt*16 + g)*40 + kl;
                unsigned af[4];
                af[0] = ldh2(Ap);
                af[1] = ldh2(Ap + 8*40);
                af[2] = ldh2(Ap + 8);
                af[3] = ldh2(Ap + 8*40 + 8);
                #pragma unroll
                for (int n8=0;n8<8;n8++) mma16h(acc[mt][n8], af, bf[n8]);
            }
        }
        __syncthreads();
    }
    // xs is dead now (last mma consumed it before the final __syncthreads above).
    // epilogue: bias, exp for k-rows, fused rowsum; write tiles to smem (NOT HBM)
    #pragma unroll
    for (int mt=0;mt<2;mt++){
        int r0 = wr*32 + mt*16 + g;   // 0..127
        int r1 = r0 + 8;
        bool isk = (r0 < 64);         // whole 16-row group is on one side of 64
        float bi0 = isk ? bk[r0] : bv[r0-64];
        float bi1 = isk ? bk[r1] : bv[r1-64];
        int rr0 = isk ? r0 : r0-64;
        int rr1 = rr0 + 8;
        __half* dst = isk ? kes : vsb;
        float s0 = 0.f, s1 = 0.f;
        #pragma unroll
        for (int n8=0;n8<8;n8++){
            int nl = wc*64 + n8*8 + 2*t4;
            float v00 = acc[mt][n8][0]+bi0, v01 = acc[mt][n8][1]+bi0;
            float v10 = acc[mt][n8][2]+bi1, v11 = acc[mt][n8][3]+bi1;
            if (isk){ v00=__expf(v00); v01=__expf(v01); v10=__expf(v10); v11=__expf(v11); }
            __half2 h0 = __floats2half2_rn(v00, v01);
            __half2 h1 = __floats2half2_rn(v10, v11);
            *(__half2*)(dst + rr0*136 + nl) = h0;
            *(__half2*)(dst + rr1*136 + nl) = h1;
            if (isk){
                s0 += __low2float(h0) + __high2float(h0);
                s1 += __low2float(h1) + __high2float(h1);
            }
        }
        if (isk){
            s0 += __shfl_xor_sync(0xffffffffu, s0, 1);
            s0 += __shfl_xor_sync(0xffffffffu, s0, 2);
            s1 += __shfl_xor_sync(0xffffffffu, s1, 1);
            s1 += __shfl_xor_sync(0xffffffffu, s1, 2);
            if (t4 == 0){
                atomicAdd(&g_rowsum[b*KD + r0], s0);
                atomicAdd(&g_rowsum[b*KD + r1], s1);
            }
        }
    }
    __syncthreads();

    // local ctx partial: ctx[d,e] = sum_{n in tile} exp(k)[d][n] * v[e][n]
    // warps 0..3 each own a 16-row d-group; K = 128 (this tile's n)
    if (warp < 4){
        float acc3[8][4];
        #pragma unroll
        for (int c=0;c<8;c++)
          #pragma unroll
          for (int k=0;k<4;k++) acc3[c][k]=0.f;
        #pragma unroll
        for (int step=0; step<8; step++){
            int kl = step*16 + t4*2;
            int m = warp*16 + g;
            unsigned af[4];
            af[0] = ldh2(kes + m*136 + kl);
            af[1] = ldh2(kes + (m+8)*136 + kl);
            af[2] = ldh2(kes + m*136 + kl + 8);
            af[3] = ldh2(kes + (m+8)*136 + kl + 8);
            #pragma unroll
            for (int n8=0;n8<8;n8++){
                int e = n8*8 + g;
                unsigned bf[2];
                bf[0] = ldh2(vsb + e*136 + kl);
                bf[1] = ldh2(vsb + e*136 + kl + 8);
                mma16h(acc3[n8], af, bf);
            }
        }
        float* outp = g_ctx_part + ((size_t)(b*32 + nt))*KD*KD;
        #pragma unroll
        for (int n8=0;n8<8;n8++){
            int r0c = warp*16 + g;
            int cc  = n8*8 + 2*t4;
            *(float2*)(outp + r0c*KD + cc)     = make_float2(acc3[n8][0], acc3[n8][1]);
            *(float2*)(outp + (r0c+8)*KD + cc) = make_float2(acc3[n8][2], acc3[n8][3]);
        }
    }
}

// ---------------- K3: reduce 32 partials, divide by rowsum (1 thread / elem) ----------------
__global__ void __launch_bounds__(256) ctx_reduce_kernel()
{
    int idx = blockIdx.x*256 + threadIdx.x;   // 0 .. 32*4096-1
    int b = idx >> 12;
    int i = idx & 4095;
    int d = i >> 6;
    float s = 0.f;
    #pragma unroll
    for (int p = 0; p < 32; p++) s += g_ctx_part[((size_t)b*32+p)*4096 + i];
    g_ctx[(size_t)b*4096 + i] = s / g_rowsum[b*KD + d];
}

// ---------------- K4: M = Wo folded with ctx -> half ----------------
__global__ void __launch_bounds__(256) m_kernel(const float* __restrict__ Wo)
{
    __shared__ float WoS[64*65];
    __shared__ float cS[64*65];
    int h = blockIdx.x, ot = blockIdx.y, b = blockIdx.z;
    int tid = threadIdx.x;
    int ty = tid >> 4, tx = tid & 15;
    for (int i = tid; i < 64*64; i += 256) {
        int r = i >> 6, e = i & 63;
        WoS[r*65+e] = Wo[(ot*64 + r)*QD + h*64 + e];
        cS[r*65+e]  = g_ctx[(size_t)b*KD*KD + r*64 + e];
    }
    __syncthreads();
    float acc[4][4] = {};
    #pragma unroll
    for (int e = 0; e < 64; e++) {
        float a[4], bb[4];
        #pragma unroll
        for (int i=0;i<4;i++) a[i] = WoS[(ty*4+i)*65+e];
        #pragma unroll
        for (int j=0;j<4;j++) bb[j] = cS[(tx*4+j)*65+e];
        #pragma unroll
        for (int i=0;i<4;i++)
            #pragma unroll
            for (int j=0;j<4;j++) acc[i][j] += a[i]*bb[j];
    }
    #pragma unroll
    for (int i=0;i<4;i++)
        #pragma unroll
        for (int j=0;j<4;j++)
            g_Mh[((size_t)b*OD + ot*64 + ty*4+i)*QD + h*64 + tx*4+j] = __float2half_rn(acc[i][j]);
}

// ---------------- K5: fused q-proj(fp16) -> softmax(d) -> out GEMM (fp16) ----------------
// grid (64, 32), 256 thr.  smem total = 148480 B  (unchanged from R13)
__global__ void __launch_bounds__(256) fused_q_out_mma(
    const float* __restrict__ x, const float* __restrict__ bq,
    const float* __restrict__ bo, float* __restrict__ out)
{
    extern __shared__ __half smh[];
    __half* xs  = smh;                  // [64][264] (phase A, transposed x)
    __half* qs  = smh;                  // [64][520] (phase B/C), aliases xs region
    __half* As  = smh + 33280;          // [2][512][40] phase A; [2][256][40] phase C
    const int nt = blockIdx.x, b = blockIdx.y;
    const int n0 = nt*64;
    const int tid = threadIdx.x;
    const int warp = tid>>5, lane = tid&31;
    const int g = lane>>2, t4 = lane&3;

    for (int i = tid; i < 256*16; i += 256) {
        int c = i>>4, n4 = (i&15)*4;
        float4 val = *(const float4*)(x + ((size_t)b*Cc + c)*Nn + n0 + n4);
        xs[(n4+0)*264 + c] = __float2half_rn(val.x);
        xs[(n4+1)*264 + c] = __float2half_rn(val.y);
        xs[(n4+2)*264 + c] = __float2half_rn(val.z);
        xs[(n4+3)*264 + c] = __float2half_rn(val.w);
    }
    #pragma unroll
    for (int j=0;j<8;j++){
        int s = tid + 256*j;
        int row = s>>2, seg = s&3;
        cpa16(As + row*40 + seg*8, g_Wqh + row*Cc + seg*8);
    }
    CP_COMMIT();

    // ---- Phase A (fp16): q = Wq @ x ; warp == head, warp tile 64x64 ----
    float acc[4][8][4];
    #pragma unroll
    for (int a=0;a<4;a++)
      #pragma unroll
      for (int c=0;c<8;c++)
        #pragma unroll
        for (int k=0;k<4;k++) acc[a][c][k]=0.f;

    const int NKA = 8;
    for (int kc=0; kc<NKA; kc++){
        if (kc+1 < NKA){
            __half* dst = As + ((kc+1)&1)*20480;
            const __half* src = g_Wqh + (kc+1)*32;
            #pragma unroll
            for (int j=0;j<8;j++){
                int s = tid + 256*j;
                int row = s>>2, seg = s&3;
                cpa16(dst + row*40 + seg*8, src + row*Cc + seg*8);
            }
            CP_COMMIT(); CP_WAIT1();
        } else CP_WAIT0();
        __syncthreads();
        const __half* A0 = As + (kc&1)*20480 + (warp*64)*40;
        #pragma unroll
        for (int sub=0; sub<2; sub++){
            int kl = sub*16 + t4*2;
            int kabs = kc*32 + kl;
            unsigned bf[8][2];
            #pragma unroll
            for (int n8=0;n8<8;n8++){
                int n = n8*8 + g;
                bf[n8][0] = ldh2(xs + n*264 + kabs);
                bf[n8][1] = ldh2(xs + n*264 + kabs + 8);
            }
            #pragma unroll
            for (int mt=0;mt<4;mt++){
                const __half* Ap = A0 + (mt*16 + g)*40 + kl;
                unsigned af[4];
                af[0] = ldh2(Ap);
                af[1] = ldh2(Ap + 8*40);
                af[2] = ldh2(Ap + 8);
                af[3] = ldh2(Ap + 8*40 + 8);
                #pragma unroll
                for (int n8=0;n8<8;n8++) mma16h(acc[mt][n8], af, bf[n8]);
            }
        }
        __syncthreads();
    }

    // ---- prefetch M chunks 0,1 into Msh (As region dead); overlaps softmax ----
    const __half* Mb = g_Mh + (size_t)b*OD*QD;
    __half* Msh = As;                   // [2][256][40]
    #pragma unroll
    for (int j=0;j<4;j++){
        int s = tid + 256*j;
        int row = s>>2, seg = s&3;
        cpa16(Msh + row*40 + seg*8, Mb + row*QD + seg*8);
    }
    CP_COMMIT();
    #pragma unroll
    for (int j=0;j<4;j++){
        int s = tid + 256*j;
        int row = s>>2, seg = s&3;
        cpa16(Msh + 10240 + row*40 + seg*8, Mb + 32 + row*QD + seg*8);
    }
    CP_COMMIT();

    // ---- Phase B: bias + exp + softmax over kd (this warp = one head) ----
    #pragma unroll
    for (int mt=0;mt<4;mt++){
        float b0 = bq[warp*64 + mt*16 + g];
        float b1 = bq[warp*64 + mt*16 + g + 8];
        #pragma unroll
        for (int n8=0;n8<8;n8++){
            acc[mt][n8][0] = __expf(acc[mt][n8][0] + b0);
            acc[mt][n8][1] = __expf(acc[mt][n8][1] + b0);
            acc[mt][n8][2] = __expf(acc[mt][n8][2] + b1);
            acc[mt][n8][3] = __expf(acc[mt][n8][3] + b1);
        }
    }
    float inv[8][2];
    #pragma unroll
    for (int n8=0;n8<8;n8++){
        #pragma unroll
        for (int p=0;p<2;p++){
            float s = 0.f;
            #pragma unroll
            for (int mt=0;mt<4;mt++) s += acc[mt][n8][p] + acc[mt][n8][p+2];
            s += __shfl_xor_sync(0xffffffffu, s, 4);
            s += __shfl_xor_sync(0xffffffffu, s, 8);
            s += __shfl_xor_sync(0xffffffffu, s, 16);
            inv[n8][p] = 1.f/s;
        }
    }
    #pragma unroll
    for (int mt=0;mt<4;mt++){
        int k0 = warp*64 + mt*16 + g;
        #pragma unroll
        for (int n8=0;n8<8;n8++){
            int n = n8*8 + 2*t4;
            qs[n*520 + k0]       = __float2half_rn(acc[mt][n8][0]*inv[n8][0]);
            qs[(n+1)*520 + k0]   = __float2half_rn(acc[mt][n8][1]*inv[n8][1]);
            qs[n*520 + k0+8]     = __float2half_rn(acc[mt][n8][2]*inv[n8][0]);
            qs[(n+1)*520 + k0+8] = __float2half_rn(acc[mt][n8][3]*inv[n8][1]);
        }
    }
    __syncthreads();

    // ---- Phase C (fp16): out = M[b] @ qs ----
    float acc2[4][4][4];
    #pragma unroll
    for (int a=0;a<4;a++)
      #pragma unroll
      for (int c=0;c<4;c++)
        #pragma unroll
        for (int k=0;k<4;k++) acc2[a][c][k]=0.f;

    const int wr = warp>>1, wc = warp&1;
    const int NKC = 16;
    for (int ki=0; ki<NKC; ki++){
        if (ki < NKC-1) CP_WAIT1(); else CP_WAIT0();
        __syncthreads();
        const __half* A0 = Msh + (ki&1)*10240 + (wr*64)*40;
        #pragma unroll
        for (int sub=0; sub<2; sub++){
            int kl = sub*16 + t4*2;
            int kabs = ki*32 + kl;
            unsigned bf[4][2];
            #pragma unroll
            for (int n8=0;n8<4;n8++){
                int n = wc*32 + n8*8 + g;
                bf[n8][0] = ldh2(qs + n*520 + kabs);
                bf[n8][1] = ldh2(qs + n*520 + kabs + 8);
            }
            #pragma unroll
            for (int mt=0;mt<4;mt++){
                const __half* Ap = A0 + (mt*16 + g)*40 + kl;
                unsigned af[4];
                af[0] = ldh2(Ap);
                af[1] = ldh2(Ap + 8*40);
                af[2] = ldh2(Ap + 8);
                af[3] = ldh2(Ap + 8*40 + 8);
                #pragma unroll
                for (int n8=0;n8<4;n8++) mma16h(acc2[mt][n8], af, bf[n8]);
            }
        }
        __syncthreads();
        if (ki + 2 < NKC){
            __half* dst = Msh + (ki&1)*10240;
            const __half* src = Mb + (ki+2)*32;
            #pragma unroll
            for (int j=0;j<4;j++){
                int s = tid + 256*j;
                int row = s>>2, seg = s&3;
                cpa16(dst + row*40 + seg*8, src + row*QD + seg*8);
            }
            CP_COMMIT();
        }
    }
    // epilogue
    #pragma unroll
    for (int mt=0;mt<4;mt++){
        int r0 = wr*64 + mt*16 + g;
        float bo0 = bo[r0], bo1 = bo[r0+8];
        #pragma unroll
        for (int n8=0;n8<4;n8++){
            int c = n0 + wc*32 + n8*8 + 2*t4;
            *(float2*)(out + ((size_t)b*OD + r0)*Nn + c) =
                make_float2(acc2[mt][n8][0]+bo0, acc2[mt][n8][1]+bo0);
            *(float2*)(out + ((size_t)b*OD + r0+8)*Nn + c) =
                make_float2(acc2[mt][n8][2]+bo1, acc2[mt][n8][3]+bo1);
        }
    }
}

// ---------------- launch ----------------
extern "C" void kernel_launch(void* const* d_in, const int* in_sizes, int n_in,
                              void* d_out, int out_size)
{
    const float* x  = (const float*)d_in[0];
    const float* Wq = (const float*)d_in[1];
    const float* bq = (const float*)d_in[2];
    const float* Wk = (const float*)d_in[3];
    const float* bk = (const float*)d_in[4];
    const float* Wv = (const float*)d_in[5];
    const float* bv = (const float*)d_in[6];
    const float* Wo = (const float*)d_in[7];
    const float* bo = (const float*)d_in[8];
    float* out = (float*)d_out;

    round_kernel<<<512, 256>>>(Wq, Wk, Wv);

    cudaFuncSetAttribute(kv_proj_ctx, cudaFuncAttributeMaxDynamicSharedMemorySize, 88064);
    kv_proj_ctx<<<dim3(32,32), 256, 88064>>>(x, bk, bv);

    ctx_reduce_kernel<<<512, 256>>>();
    m_kernel<<<dim3(8,4,32), 256>>>(Wo);

    cudaFuncSetAttribute(fused_q_out_mma, cudaFuncAttributeMaxDynamicSharedMemorySize, 148480);
    fused_q_out_mma<<<dim3(64,32), 256, 148480>>>(x, bq, bo, out);
}

// round 15
// speedup vs baseline: 1.0483x; 1.0236x over previous
#include <cuda_runtime.h>
#include <cuda_fp16.h>
#include <math.h>

#define Bb 32
#define Cc 256
#define Nn 4096
#define KD 64
#define HEADS 8
#define QD 512
#define OD 256

// ---------------- scratch (device globals; allocation-free) ----------------
__device__ __align__(256) float  g_rowsum[Bb*KD];
__device__ __align__(256) float  g_ctx_part[(size_t)Bb*32*KD*KD];  // 32 n-splits per batch
__device__ __align__(256) float  g_ctx[(size_t)Bb*KD*KD];
__device__ __align__(256) __half g_Mh[(size_t)Bb*OD*QD];     // folded Wo*ctx, half
__device__ __align__(256) __half g_Wqh[QD*Cc];               // half Wq
__device__ __align__(256) __half g_Wkvh[128*Cc];             // half [Wk; Wv]

// ---------------- helpers ----------------
__device__ __forceinline__ void mma16h(float* d, const unsigned* a, const unsigned* b){
    asm volatile("mma.sync.aligned.m16n8k16.row.col.f32.f16.f16.f32 "
        "{%0,%1,%2,%3}, {%4,%5,%6,%7}, {%8,%9}, {%0,%1,%2,%3};"
        : "+f"(d[0]), "+f"(d[1]), "+f"(d[2]), "+f"(d[3])
        : "r"(a[0]), "r"(a[1]), "r"(a[2]), "r"(a[3]), "r"(b[0]), "r"(b[1]));
}
__device__ __forceinline__ void cpa16(void* smem_dst, const void* gsrc){
    unsigned s = (unsigned)__cvta_generic_to_shared(smem_dst);
    asm volatile("cp.async.cg.shared.global [%0], [%1], 16;" :: "r"(s), "l"(gsrc));
}
#define CP_COMMIT() asm volatile("cp.async.commit_group;")
#define CP_WAIT1()  asm volatile("cp.async.wait_group 1;")
#define CP_WAIT0()  asm volatile("cp.async.wait_group 0;")
__device__ __forceinline__ unsigned ldh2(const __half* p){ return *(const unsigned*)p; }

// ---------------- K0: convert weights to half, zero rowsum ----------------
__global__ void __launch_bounds__(256) round_kernel(
    const float* __restrict__ Wq, const float* __restrict__ Wk, const float* __restrict__ Wv)
{
    int i = blockIdx.x*256 + threadIdx.x;
    if (i < QD*Cc) g_Wqh[i] = __float2half_rn(Wq[i]);
    if (i < KD*Cc) { g_Wkvh[i] = __float2half_rn(Wk[i]); g_Wkvh[KD*Cc + i] = __float2half_rn(Wv[i]); }
    if (i < Bb*KD) g_rowsum[i] = 0.f;
}

// ---------------- K1: fused kv projection + exp + rowsum + local ctx partial ----------------
// grid (32 ntiles of 128, 32 b), 256 thr. smem: xs half[128][264] + As half[2][128][40] = 88064 B
__global__ void __launch_bounds__(256) kv_proj_ctx(
    const float* __restrict__ x, const float* __restrict__ bk, const float* __restrict__ bv)
{
    extern __shared__ __half smk[];
    __half* xs = smk;                 // [n=128][c=264] (phase 1)
    __half* kes = smk;                // [64][136] exp(k)  (phase 2, aliases xs)
    __half* vsb = smk + 64*136;       // [64][136] v       (phase 2)
    __half* As = smk + 128*264;       // [2][128][40] W staging
    const int nt = blockIdx.x, b = blockIdx.y;
    const int n0 = nt*128;
    const int tid = threadIdx.x;
    const int warp = tid>>5, lane = tid&31;
    const int g = lane>>2, t4 = lane&3;
    const int wr = warp>>1, wc = warp&1;

    // load x tile [256 c][128 n], store transposed as half
    for (int i = tid; i < 256*32; i += 256) {
        int c = i>>5, n4 = (i&31)*4;
        float4 val = *(const float4*)(x + ((size_t)b*Cc + c)*Nn + n0 + n4);
        xs[(n4+0)*264 + c] = __float2half_rn(val.x);
        xs[(n4+1)*264 + c] = __float2half_rn(val.y);
        xs[(n4+2)*264 + c] = __float2half_rn(val.z);
        xs[(n4+3)*264 + c] = __float2half_rn(val.w);
    }
    #pragma unroll
    for (int j=0;j<2;j++){
        int s = tid + 256*j;
        int row = s>>2, seg = s&3;
        cpa16(As + row*40 + seg*8, g_Wkvh + row*Cc + seg*8);
    }
    CP_COMMIT();

    float acc[2][8][4];
    #pragma unroll
    for (int a=0;a<2;a++)
      #pragma unroll
      for (int c=0;c<8;c++)
        #pragma unroll
        for (int k=0;k<4;k++) acc[a][c][k]=0.f;

    const int NK = 8;
    for (int kc=0; kc<NK; kc++){
        if (kc+1 < NK){
            __half* dst = As + ((kc+1)&1)*5120;
            const __half* src = g_Wkvh + (kc+1)*32;
            #pragma unroll
            for (int j=0;j<2;j++){
                int s = tid + 256*j;
                int row = s>>2, seg = s&3;
                cpa16(dst + row*40 + seg*8, src + row*Cc + seg*8);
            }
            CP_COMMIT(); CP_WAIT1();
        } else CP_WAIT0();
        __syncthreads();
        const __half* A0 = As + (kc&1)*5120 + (wr*32)*40;
        #pragma unroll
        for (int sub=0; sub<2; sub++){
            int kl = sub*16 + t4*2;
            int kabs = kc*32 + kl;
            unsigned bf[8][2];
            #pragma unroll
            for (int n8=0;n8<8;n8++){
                int n = wc*64 + n8*8 + g;
                bf[n8][0] = ldh2(xs + n*264 + kabs);
                bf[n8][1] = ldh2(xs + n*264 + kabs + 8);
            }
            #pragma unroll
            for (int mt=0;mt<2;mt++){
                const __half* Ap = A0 + (mt*16 + g)*40 + kl;
                unsigned af[4];
                af[0] = ldh2(Ap);
                af[1] = ldh2(Ap + 8*40);
                af[2] = ldh2(Ap + 8);
                af[3] = ldh2(Ap + 8*40 + 8);
                #pragma unroll
                for (int n8=0;n8<8;n8++) mma16h(acc[mt][n8], af, bf[n8]);
            }
        }
        __syncthreads();
    }
    // epilogue: bias, exp for k-rows, fused rowsum; write tiles to smem (NOT HBM)
    #pragma unroll
    for (int mt=0;mt<2;mt++){
        int r0 = wr*32 + mt*16 + g;
        int r1 = r0 + 8;
        bool isk = (r0 < 64);
        float bi0 = isk ? bk[r0] : bv[r0-64];
        float bi1 = isk ? bk[r1] : bv[r1-64];
        int rr0 = isk ? r0 : r0-64;
        int rr1 = rr0 + 8;
        __half* dst = isk ? kes : vsb;
        float s0 = 0.f, s1 = 0.f;
        #pragma unroll
        for (int n8=0;n8<8;n8++){
            int nl = wc*64 + n8*8 + 2*t4;
            float v00 = acc[mt][n8][0]+bi0, v01 = acc[mt][n8][1]+bi0;
            float v10 = acc[mt][n8][2]+bi1, v11 = acc[mt][n8][3]+bi1;
            if (isk){ v00=__expf(v00); v01=__expf(v01); v10=__expf(v10); v11=__expf(v11); }
            __half2 h0 = __floats2half2_rn(v00, v01);
            __half2 h1 = __floats2half2_rn(v10, v11);
            *(__half2*)(dst + rr0*136 + nl) = h0;
            *(__half2*)(dst + rr1*136 + nl) = h1;
            if (isk){
                s0 += __low2float(h0) + __high2float(h0);
                s1 += __low2float(h1) + __high2float(h1);
            }
        }
        if (isk){
            s0 += __shfl_xor_sync(0xffffffffu, s0, 1);
            s0 += __shfl_xor_sync(0xffffffffu, s0, 2);
            s1 += __shfl_xor_sync(0xffffffffu, s1, 1);
            s1 += __shfl_xor_sync(0xffffffffu, s1, 2);
            if (t4 == 0){
                atomicAdd(&g_rowsum[b*KD + r0], s0);
                atomicAdd(&g_rowsum[b*KD + r1], s1);
            }
        }
    }
    __syncthreads();

    // local ctx partial: warps 0..3, 16 d-rows each, K = 128
    if (warp < 4){
        float acc3[8][4];
        #pragma unroll
        for (int c=0;c<8;c++)
          #pragma unroll
          for (int k=0;k<4;k++) acc3[c][k]=0.f;
        #pragma unroll
        for (int step=0; step<8; step++){
            int kl = step*16 + t4*2;
            int m = warp*16 + g;
            unsigned af[4];
            af[0] = ldh2(kes + m*136 + kl);
            af[1] = ldh2(kes + (m+8)*136 + kl);
            af[2] = ldh2(kes + m*136 + kl + 8);
            af[3] = ldh2(kes + (m+8)*136 + kl + 8);
            #pragma unroll
            for (int n8=0;n8<8;n8++){
                int e = n8*8 + g;
                unsigned bf[2];
                bf[0] = ldh2(vsb + e*136 + kl);
                bf[1] = ldh2(vsb + e*136 + kl + 8);
                mma16h(acc3[n8], af, bf);
            }
        }
        float* outp = g_ctx_part + ((size_t)(b*32 + nt))*KD*KD;
        #pragma unroll
        for (int n8=0;n8<8;n8++){
            int r0c = warp*16 + g;
            int cc  = n8*8 + 2*t4;
            *(float2*)(outp + r0c*KD + cc)     = make_float2(acc3[n8][0], acc3[n8][1]);
            *(float2*)(outp + (r0c+8)*KD + cc) = make_float2(acc3[n8][2], acc3[n8][3]);
        }
    }
}

// ---------------- K3: reduce 32 partials, divide by rowsum (1 thread / elem) ----------------
__global__ void __launch_bounds__(256) ctx_reduce_kernel()
{
    int idx = blockIdx.x*256 + threadIdx.x;
    int b = idx >> 12;
    int i = idx & 4095;
    int d = i >> 6;
    float s = 0.f;
    #pragma unroll
    for (int p = 0; p < 32; p++) s += g_ctx_part[((size_t)b*32+p)*4096 + i];
    g_ctx[(size_t)b*4096 + i] = s / g_rowsum[b*KD + d];
}

// ---------------- K4: M = Wo folded with ctx -> half (fp16 MMA) ----------------
// grid (8 h, 32 b), 256 thr. Each block: M[b, 0..255, h*64..h*64+63].
// smem: WoS half[256][72] + cS half[64][72] = 46080 B (static)
__global__ void __launch_bounds__(256) m_kernel_h(const float* __restrict__ Wo)
{
    __shared__ __align__(16) __half WoS[256*72];
    __shared__ __align__(16) __half cS[64*72];
    const int h = blockIdx.x, b = blockIdx.y;
    const int tid = threadIdx.x;
    const int warp = tid>>5, lane = tid&31;
    const int g = lane>>2, t4 = lane&3;

    // stage Wo block [256 o][64 e] as half
    for (int i = tid; i < 4096; i += 256){
        int o = i>>4, e4 = (i&15)*4;
        float4 v = *(const float4*)(Wo + (size_t)o*QD + h*64 + e4);
        __half* d = WoS + o*72 + e4;
        d[0]=__float2half_rn(v.x); d[1]=__float2half_rn(v.y);
        d[2]=__float2half_rn(v.z); d[3]=__float2half_rn(v.w);
    }
    // stage ctx [64 d][64 e] as half
    for (int i = tid; i < 1024; i += 256){
        int dd = i>>4, e4 = (i&15)*4;
        float4 v = *(const float4*)(g_ctx + (size_t)b*4096 + dd*64 + e4);
        __half* d = cS + dd*72 + e4;
        d[0]=__float2half_rn(v.x); d[1]=__float2half_rn(v.y);
        d[2]=__float2half_rn(v.z); d[3]=__float2half_rn(v.w);
    }
    __syncthreads();

    // warp tile: 32 o-rows x 64 d; K = 64 (e)
    float acc[2][8][4];
    #pragma unroll
    for (int a=0;a<2;a++)
      #pragma unroll
      for (int c=0;c<8;c++)
        #pragma unroll
        for (int k=0;k<4;k++) acc[a][c][k]=0.f;

    #pragma unroll
    for (int step=0; step<4; step++){
        int kl = step*16 + t4*2;
        unsigned bf[8][2];
        #pragma unroll
        for (int n8=0;n8<8;n8++){
            int dd = n8*8 + g;
            bf[n8][0] = ldh2(cS + dd*72 + kl);
            bf[n8][1] = ldh2(cS + dd*72 + kl + 8);
        }
        #pragma unroll
        for (int mt=0;mt<2;mt++){
            const __half* Ap = WoS + (warp*32 + mt*16 + g)*72 + kl;
            unsigned af[4];
            af[0] = ldh2(Ap);
            af[1] = ldh2(Ap + 8*72);
            af[2] = ldh2(Ap + 8);
            af[3] = ldh2(Ap + 8*72 + 8);
            #pragma unroll
            for (int n8=0;n8<8;n8++) mma16h(acc[mt][n8], af, bf[n8]);
        }
    }
    // store M half: rows o, cols h*64 + d
    #pragma unroll
    for (int mt=0;mt<2;mt++){
        int r0 = warp*32 + mt*16 + g;
        int r1 = r0 + 8;
        #pragma unroll
        for (int n8=0;n8<8;n8++){
            int c = h*64 + n8*8 + 2*t4;
            *(__half2*)(g_Mh + ((size_t)b*OD + r0)*QD + c) =
                __floats2half2_rn(acc[mt][n8][0], acc[mt][n8][1]);
            *(__half2*)(g_Mh + ((size_t)b*OD + r1)*QD + c) =
                __floats2half2_rn(acc[mt][n8][2], acc[mt][n8][3]);
        }
    }
}

// ---------------- K5: fused q-proj(fp16) -> softmax(d) -> out GEMM (fp16) ----------------
// grid (64, 32), 256 thr.  smem total = 148480 B
__global__ void __launch_bounds__(256) fused_q_out_mma(
    const float* __restrict__ x, const float* __restrict__ bq,
    const float* __restrict__ bo, float* __restrict__ out)
{
    extern __shared__ __half smh[];
    __half* xs  = smh;                  // [64][264] (phase A, transposed x)
    __half* qs  = smh;                  // [64][520] (phase B/C), aliases xs region
    __half* As  = smh + 33280;          // [2][512][40] phase A; [2][256][40] phase C
    const int nt = blockIdx.x, b = blockIdx.y;
    const int n0 = nt*64;
    const int tid = threadIdx.x;
    const int warp = tid>>5, lane = tid&31;
    const int g = lane>>2, t4 = lane&3;

    for (int i = tid; i < 256*16; i += 256) {
        int c = i>>4, n4 = (i&15)*4;
        float4 val = *(const float4*)(x + ((size_t)b*Cc + c)*Nn + n0 + n4);
        xs[(n4+0)*264 + c] = __float2half_rn(val.x);
        xs[(n4+1)*264 + c] = __float2half_rn(val.y);
        xs[(n4+2)*264 + c] = __float2half_rn(val.z);
        xs[(n4+3)*264 + c] = __float2half_rn(val.w);
    }
    #pragma unroll
    for (int j=0;j<8;j++){
        int s = tid + 256*j;
        int row = s>>2, seg = s&3;
        cpa16(As + row*40 + seg*8, g_Wqh + row*Cc + seg*8);
    }
    CP_COMMIT();

    // ---- Phase A (fp16): q = Wq @ x ; warp == head, warp tile 64x64 ----
    float acc[4][8][4];
    #pragma unroll
    for (int a=0;a<4;a++)
      #pragma unroll
      for (int c=0;c<8;c++)
        #pragma unroll
        for (int k=0;k<4;k++) acc[a][c][k]=0.f;

    const int NKA = 8;
    for (int kc=0; kc<NKA; kc++){
        if (kc+1 < NKA){
            __half* dst = As + ((kc+1)&1)*20480;
            const __half* src = g_Wqh + (kc+1)*32;
            #pragma unroll
            for (int j=0;j<8;j++){
                int s = tid + 256*j;
                int row = s>>2, seg = s&3;
                cpa16(dst + row*40 + seg*8, src + row*Cc + seg*8);
            }
            CP_COMMIT(); CP_WAIT1();
        } else CP_WAIT0();
        __syncthreads();
        const __half* A0 = As + (kc&1)*20480 + (warp*64)*40;
        #pragma unroll
        for (int sub=0; sub<2; sub++){
            int kl = sub*16 + t4*2;
            int kabs = kc*32 + kl;
            unsigned bf[8][2];
            #pragma unroll
            for (int n8=0;n8<8;n8++){
                int n = n8*8 + g;
                bf[n8][0] = ldh2(xs + n*264 + kabs);
                bf[n8][1] = ldh2(xs + n*264 + kabs + 8);
            }
            #pragma unroll
            for (int mt=0;mt<4;mt++){
                const __half* Ap = A0 + (mt*16 + g)*40 + kl;
                unsigned af[4];
                af[0] = ldh2(Ap);
                af[1] = ldh2(Ap + 8*40);
                af[2] = ldh2(Ap + 8);
                af[3] = ldh2(Ap + 8*40 + 8);
                #pragma unroll
                for (int n8=0;n8<8;n8++) mma16h(acc[mt][n8], af, bf[n8]);
            }
        }
        __syncthreads();
    }

    // ---- prefetch M chunks 0,1 into Msh (As region dead); overlaps softmax ----
    const __half* Mb = g_Mh + (size_t)b*OD*QD;
    __half* Msh = As;                   // [2][256][40]
    #pragma unroll
    for (int j=0;j<4;j++){
        int s = tid + 256*j;
        int row = s>>2, seg = s&3;
        cpa16(Msh + row*40 + seg*8, Mb + row*QD + seg*8);
    }
    CP_COMMIT();
    #pragma unroll
    for (int j=0;j<4;j++){
        int s = tid + 256*j;
        int row = s>>2, seg = s&3;
        cpa16(Msh + 10240 + row*40 + seg*8, Mb + 32 + row*QD + seg*8);
    }
    CP_COMMIT();

    // ---- Phase B: bias + exp + softmax over kd (this warp = one head) ----
    #pragma unroll
    for (int mt=0;mt<4;mt++){
        float b0 = bq[warp*64 + mt*16 + g];
        float b1 = bq[warp*64 + mt*16 + g + 8];
        #pragma unroll
        for (int n8=0;n8<8;n8++){
            acc[mt][n8][0] = __expf(acc[mt][n8][0] + b0);
            acc[mt][n8][1] = __expf(acc[mt][n8][1] + b0);
            acc[mt][n8][2] = __expf(acc[mt][n8][2] + b1);
            acc[mt][n8][3] = __expf(acc[mt][n8][3] + b1);
        }
    }
    float inv[8][2];
    #pragma unroll
    for (int n8=0;n8<8;n8++){
        #pragma unroll
        for (int p=0;p<2;p++){
            float s = 0.f;
            #pragma unroll
            for (int mt=0;mt<4;mt++) s += acc[mt][n8][p] + acc[mt][n8][p+2];
            s += __shfl_xor_sync(0xffffffffu, s, 4);
            s += __shfl_xor_sync(0xffffffffu, s, 8);
            s += __shfl_xor_sync(0xffffffffu, s, 16);
            inv[n8][p] = 1.f/s;
        }
    }
    #pragma unroll
    for (int mt=0;mt<4;mt++){
        int k0 = warp*64 + mt*16 + g;
        #pragma unroll
        for (int n8=0;n8<8;n8++){
            int n = n8*8 + 2*t4;
            qs[n*520 + k0]       = __float2half_rn(acc[mt][n8][0]*inv[n8][0]);
            qs[(n+1)*520 + k0]   = __float2half_rn(acc[mt][n8][1]*inv[n8][1]);
            qs[n*520 + k0+8]     = __float2half_rn(acc[mt][n8][2]*inv[n8][0]);
            qs[(n+1)*520 + k0+8] = __float2half_rn(acc[mt][n8][3]*inv[n8][1]);
        }
    }
    __syncthreads();

    // ---- Phase C (fp16): out = M[b] @ qs ----
    float acc2[4][4][4];
    #pragma unroll
    for (int a=0;a<4;a++)
      #pragma unroll
      for (int c=0;c<4;c++)
        #pragma unroll
        for (int k=0;k<4;k++) acc2[a][c][k]=0.f;

    const int wr = warp>>1, wc = warp&1;
    const int NKC = 16;
    for (int ki=0; ki<NKC; ki++){
        if (ki < NKC-1) CP_WAIT1(); else CP_WAIT0();
        __syncthreads();
        const __half* A0 = Msh + (ki&1)*10240 + (wr*64)*40;
        #pragma unroll
        for (int sub=0; sub<2; sub++){
            int kl = sub*16 + t4*2;
            int kabs = ki*32 + kl;
            unsigned bf[4][2];
            #pragma unroll
            for (int n8=0;n8<4;n8++){
                int n = wc*32 + n8*8 + g;
                bf[n8][0] = ldh2(qs + n*520 + kabs);
                bf[n8][1] = ldh2(qs + n*520 + kabs + 8);
            }
            #pragma unroll
            for (int mt=0;mt<4;mt++){
                const __half* Ap = A0 + (mt*16 + g)*40 + kl;
                unsigned af[4];
                af[0] = ldh2(Ap);
                af[1] = ldh2(Ap + 8*40);
                af[2] = ldh2(Ap + 8);
                af[3] = ldh2(Ap + 8*40 + 8);
                #pragma unroll
                for (int n8=0;n8<4;n8++) mma16h(acc2[mt][n8], af, bf[n8]);
            }
        }
        __syncthreads();
        if (ki + 2 < NKC){
            __half* dst = Msh + (ki&1)*10240;
            const __half* src = Mb + (ki+2)*32;
            #pragma unroll
            for (int j=0;j<4;j++){
                int s = tid + 256*j;
                int row = s>>2, seg = s&3;
                cpa16(dst + row*40 + seg*8, src + row*QD + seg*8);
            }
            CP_COMMIT();
        }
    }
    // epilogue
    #pragma unroll
    for (int mt=0;mt<4;mt++){
        int r0 = wr*64 + mt*16 + g;
        float bo0 = bo[r0], bo1 = bo[r0+8];
        #pragma unroll
        for (int n8=0;n8<4;n8++){
            int c = n0 + wc*32 + n8*8 + 2*t4;
            *(float2*)(out + ((size_t)b*OD + r0)*Nn + c) =
                make_float2(acc2[mt][n8][0]+bo0, acc2[mt][n8][1]+bo0);
            *(float2*)(out + ((size_t)b*OD + r0+8)*Nn + c) =
                make_float2(acc2[mt][n8][2]+bo1, acc2[mt][n8][3]+bo1);
        }
    }
}

// ---------------- launch ----------------
extern "C" void kernel_launch(void* const* d_in, const int* in_sizes, int n_in,
                              void* d_out, int out_size)
{
    const float* x  = (const float*)d_in[0];
    const float* Wq = (const float*)d_in[1];
    const float* bq = (const float*)d_in[2];
    const float* Wk = (const float*)d_in[3];
    const float* bk = (const float*)d_in[4];
    const float* Wv = (const float*)d_in[5];
    const float* bv = (const float*)d_in[6];
    const float* Wo = (const float*)d_in[7];
    const float* bo = (const float*)d_in[8];
    float* out = (float*)d_out;

    round_kernel<<<512, 256>>>(Wq, Wk, Wv);

    cudaFuncSetAttribute(kv_proj_ctx, cudaFuncAttributeMaxDynamicSharedMemorySize, 88064);
    kv_proj_ctx<<<dim3(32,32), 256, 88064>>>(x, bk, bv);

    ctx_reduce_kernel<<<512, 256>>>();
    m_kernel_h<<<dim3(8,32), 256>>>(Wo);

    cudaFuncSetAttribute(fused_q_out_mma, cudaFuncAttributeMaxDynamicSharedMemorySize, 148480);
    fused_q_out_mma<<<dim3(64,32), 256, 148480>>>(x, bq, bo, out);
}

// round 17
// speedup vs baseline: 1.0641x; 1.0151x over previous
#include <cuda_runtime.h>
#include <cuda_fp16.h>
#include <math.h>

#define Bb 32
#define Cc 256
#define Nn 4096
#define KD 64
#define HEADS 8
#define QD 512
#define OD 256

// ---------------- scratch (device globals; allocation-free) ----------------
__device__ __align__(256) float  g_rowsum[Bb*KD];
__device__ __align__(256) float  g_ctx[(size_t)Bb*KD*KD];    // atomic-accumulated
__device__ __align__(256) __half g_Mh[(size_t)Bb*OD*QD];     // folded Wo*ctx, half
__device__ __align__(256) __half g_Wqh[QD*Cc];               // half Wq
__device__ __align__(256) __half g_Wkvh[128*Cc];             // half [Wk; Wv]
__device__ __align__(256) __half g_Woh[OD*QD];               // half Wo

// ---------------- helpers ----------------
__device__ __forceinline__ void mma16h(float* d, const unsigned* a, const unsigned* b){
    asm volatile("mma.sync.aligned.m16n8k16.row.col.f32.f16.f16.f32 "
        "{%0,%1,%2,%3}, {%4,%5,%6,%7}, {%8,%9}, {%0,%1,%2,%3};"
        : "+f"(d[0]), "+f"(d[1]), "+f"(d[2]), "+f"(d[3])
        : "r"(a[0]), "r"(a[1]), "r"(a[2]), "r"(a[3]), "r"(b[0]), "r"(b[1]));
}
__device__ __forceinline__ void cpa16(void* smem_dst, const void* gsrc){
    unsigned s = (unsigned)__cvta_generic_to_shared(smem_dst);
    asm volatile("cp.async.cg.shared.global [%0], [%1], 16;" :: "r"(s), "l"(gsrc));
}
#define CP_COMMIT() asm volatile("cp.async.commit_group;")
#define CP_WAIT1()  asm volatile("cp.async.wait_group 1;")
#define CP_WAIT0()  asm volatile("cp.async.wait_group 0;")
__device__ __forceinline__ unsigned ldh2(const __half* p){ return *(const unsigned*)p; }

// ---------------- K0: convert weights to half, zero accumulators ----------------
__global__ void __launch_bounds__(256) round_kernel(
    const float* __restrict__ Wq, const float* __restrict__ Wk, const float* __restrict__ Wv,
    const float* __restrict__ Wo)
{
    int i = blockIdx.x*256 + threadIdx.x;                     // 0 .. 131071
    if (i < QD*Cc) g_Wqh[i] = __float2half_rn(Wq[i]);
    if (i < KD*Cc) { g_Wkvh[i] = __float2half_rn(Wk[i]); g_Wkvh[KD*Cc + i] = __float2half_rn(Wv[i]); }
    if (i < OD*QD) g_Woh[i] = __float2half_rn(Wo[i]);
    if (i < Bb*KD) g_rowsum[i] = 0.f;
    if (i < Bb*KD*KD) g_ctx[i] = 0.f;
}

// ---------------- K1: fused kv projection + exp + rowsum + ctx atomic accum ----------------
// grid (32 ntiles of 128, 32 b), 256 thr. smem: xs half[128][264] + As half[2][128][40] = 88064 B
__global__ void __launch_bounds__(256) kv_proj_ctx(
    const float* __restrict__ x, const float* __restrict__ bk, const float* __restrict__ bv)
{
    extern __shared__ __half smk[];
    __half* xs = smk;                 // [n=128][c=264] (phase 1)
    __half* kes = smk;                // [64][136] exp(k)  (phase 2, aliases xs)
    __half* vsb = smk + 64*136;       // [64][136] v       (phase 2)
    __half* As = smk + 128*264;       // [2][128][40] W staging
    const int nt = blockIdx.x, b = blockIdx.y;
    const int n0 = nt*128;
    const int tid = threadIdx.x;
    const int warp = tid>>5, lane = tid&31;
    const int g = lane>>2, t4 = lane&3;
    const int wr = warp>>1, wc = warp&1;

    // prefetch W chunk 0 FIRST (overlaps with synchronous x load below)
    #pragma unroll
    for (int j=0;j<2;j++){
        int s = tid + 256*j;
        int row = s>>2, seg = s&3;
        cpa16(As + row*40 + seg*8, g_Wkvh + row*Cc + seg*8);
    }
    CP_COMMIT();

    // load x tile [256 c][128 n], store transposed as half
    for (int i = tid; i < 256*32; i += 256) {
        int c = i>>5, n4 = (i&31)*4;
        float4 val = *(const float4*)(x + ((size_t)b*Cc + c)*Nn + n0 + n4);
        xs[(n4+0)*264 + c] = __float2half_rn(val.x);
        xs[(n4+1)*264 + c] = __float2half_rn(val.y);
        xs[(n4+2)*264 + c] = __float2half_rn(val.z);
        xs[(n4+3)*264 + c] = __float2half_rn(val.w);
    }

    float acc[2][8][4];
    #pragma unroll
    for (int a=0;a<2;a++)
      #pragma unroll
      for (int c=0;c<8;c++)
        #pragma unroll
        for (int k=0;k<4;k++) acc[a][c][k]=0.f;

    const int NK = 8;
    for (int kc=0; kc<NK; kc++){
        if (kc+1 < NK){
            __half* dst = As + ((kc+1)&1)*5120;
            const __half* src = g_Wkvh + (kc+1)*32;
            #pragma unroll
            for (int j=0;j<2;j++){
                int s = tid + 256*j;
                int row = s>>2, seg = s&3;
                cpa16(dst + row*40 + seg*8, src + row*Cc + seg*8);
            }
            CP_COMMIT(); CP_WAIT1();
        } else CP_WAIT0();
        __syncthreads();
        const __half* A0 = As + (kc&1)*5120 + (wr*32)*40;
        #pragma unroll
        for (int sub=0; sub<2; sub++){
            int kl = sub*16 + t4*2;
            int kabs = kc*32 + kl;
            unsigned bf[8][2];
            #pragma unroll
            for (int n8=0;n8<8;n8++){
                int n = wc*64 + n8*8 + g;
                bf[n8][0] = ldh2(xs + n*264 + kabs);
                bf[n8][1] = ldh2(xs + n*264 + kabs + 8);
            }
            #pragma unroll
            for (int mt=0;mt<2;mt++){
                const __half* Ap = A0 + (mt*16 + g)*40 + kl;
                unsigned af[4];
                af[0] = ldh2(Ap);
                af[1] = ldh2(Ap + 8*40);
                af[2] = ldh2(Ap + 8);
                af[3] = ldh2(Ap + 8*40 + 8);
                #pragma unroll
                for (int n8=0;n8<8;n8++) mma16h(acc[mt][n8], af, bf[n8]);
            }
        }
        __syncthreads();
    }
    // epilogue: bias, exp for k-rows, fused rowsum; write tiles to smem (NOT HBM)
    #pragma unroll
    for (int mt=0;mt<2;mt++){
        int r0 = wr*32 + mt*16 + g;
        int r1 = r0 + 8;
        bool isk = (r0 < 64);
        float bi0 = isk ? bk[r0] : bv[r0-64];
        float bi1 = isk ? bk[r1] : bv[r1-64];
        int rr0 = isk ? r0 : r0-64;
        int rr1 = rr0 + 8;
        __half* dst = isk ? kes : vsb;
        float s0 = 0.f, s1 = 0.f;
        #pragma unroll
        for (int n8=0;n8<8;n8++){
            int nl = wc*64 + n8*8 + 2*t4;
            float v00 = acc[mt][n8][0]+bi0, v01 = acc[mt][n8][1]+bi0;
            float v10 = acc[mt][n8][2]+bi1, v11 = acc[mt][n8][3]+bi1;
            if (isk){ v00=__expf(v00); v01=__expf(v01); v10=__expf(v10); v11=__expf(v11); }
            __half2 h0 = __floats2half2_rn(v00, v01);
            __half2 h1 = __floats2half2_rn(v10, v11);
            *(__half2*)(dst + rr0*136 + nl) = h0;
            *(__half2*)(dst + rr1*136 + nl) = h1;
            if (isk){
                s0 += __low2float(h0) + __high2float(h0);
                s1 += __low2float(h1) + __high2float(h1);
            }
        }
        if (isk){
            s0 += __shfl_xor_sync(0xffffffffu, s0, 1);
            s0 += __shfl_xor_sync(0xffffffffu, s0, 2);
            s1 += __shfl_xor_sync(0xffffffffu, s1, 1);
            s1 += __shfl_xor_sync(0xffffffffu, s1, 2);
            if (t4 == 0){
                atomicAdd(&g_rowsum[b*KD + r0], s0);
                atomicAdd(&g_rowsum[b*KD + r1], s1);
            }
        }
    }
    __syncthreads();

    // local ctx partial: warps 0..3, 16 d-rows each, K = 128 -> atomicAdd into g_ctx
    if (warp < 4){
        float acc3[8][4];
        #pragma unroll
        for (int c=0;c<8;c++)
          #pragma unroll
          for (int k=0;k<4;k++) acc3[c][k]=0.f;
        #pragma unroll
        for (int step=0; step<8; step++){
            int kl = step*16 + t4*2;
            int m = warp*16 + g;
            unsigned af[4];
            af[0] = ldh2(kes + m*136 + kl);
            af[1] = ldh2(kes + (m+8)*136 + kl);
            af[2] = ldh2(kes + m*136 + kl + 8);
            af[3] = ldh2(kes + (m+8)*136 + kl + 8);
            #pragma unroll
            for (int n8=0;n8<8;n8++){
                int e = n8*8 + g;
                unsigned bf[2];
                bf[0] = ldh2(vsb + e*136 + kl);
                bf[1] = ldh2(vsb + e*136 + kl + 8);
                mma16h(acc3[n8], af, bf);
            }
        }
        float* outp = g_ctx + (size_t)b*4096;
        #pragma unroll
        for (int n8=0;n8<8;n8++){
            int r0c = warp*16 + g;
            int cc  = n8*8 + 2*t4;
            atomicAdd(outp + r0c*KD + cc,       acc3[n8][0]);
            atomicAdd(outp + r0c*KD + cc + 1,   acc3[n8][1]);
            atomicAdd(outp + (r0c+8)*KD + cc,   acc3[n8][2]);
            atomicAdd(outp + (r0c+8)*KD + cc+1, acc3[n8][3]);
        }
    }
}

// ---------------- K4: M = Wo folded with ctx/rowsum -> half (fp16 MMA) ----------------
// grid (8 h, 32 b), 256 thr. Each block: M[b, 0..255, h*64..h*64+63].
// smem: WoS half[256][72] + cS half[64][72] = 46080 B (static)
__global__ void __launch_bounds__(256) m_kernel_h()
{
    __shared__ __align__(16) __half WoS[256*72];
    __shared__ __align__(16) __half cS[64*72];
    const int h = blockIdx.x, b = blockIdx.y;
    const int tid = threadIdx.x;
    const int warp = tid>>5, lane = tid&31;
    const int g = lane>>2, t4 = lane&3;

    // async-stage Wo block [256 o][64 e] from half weights
    for (int i = tid; i < 2048; i += 256){
        int o = i>>3, seg = i&7;
        cpa16(WoS + o*72 + seg*8, g_Woh + (size_t)o*QD + h*64 + seg*8);
    }
    CP_COMMIT();
    // stage ctx [64 d][64 e] as half, dividing by rowsum (overlaps the cp.async)
    for (int i = tid; i < 1024; i += 256){
        int dd = i>>4, e4 = (i&15)*4;
        float4 v = *(const float4*)(g_ctx + (size_t)b*4096 + dd*64 + e4);
        float inv = 1.f / g_rowsum[b*KD + dd];
        __half* d = cS + dd*72 + e4;
        d[0]=__float2half_rn(v.x*inv); d[1]=__float2half_rn(v.y*inv);
        d[2]=__float2half_rn(v.z*inv); d[3]=__float2half_rn(v.w*inv);
    }
    CP_WAIT0();
    __syncthreads();

    // warp tile: 32 o-rows x 64 d; K = 64 (e)
    float acc[2][8][4];
    #pragma unroll
    for (int a=0;a<2;a++)
      #pragma unroll
      for (int c=0;c<8;c++)
        #pragma unroll
        for (int k=0;k<4;k++) acc[a][c][k]=0.f;

    #pragma unroll
    for (int step=0; step<4; step++){
        int kl = step*16 + t4*2;
        unsigned bf[8][2];
        #pragma unroll
        for (int n8=0;n8<8;n8++){
            int dd = n8*8 + g;
            bf[n8][0] = ldh2(cS + dd*72 + kl);
            bf[n8][1] = ldh2(cS + dd*72 + kl + 8);
        }
        #pragma unroll
        for (int mt=0;mt<2;mt++){
            const __half* Ap = WoS + (warp*32 + mt*16 + g)*72 + kl;
            unsigned af[4];
            af[0] = ldh2(Ap);
            af[1] = ldh2(Ap + 8*72);
            af[2] = ldh2(Ap + 8);
            af[3] = ldh2(Ap + 8*72 + 8);
            #pragma unroll
            for (int n8=0;n8<8;n8++) mma16h(acc[mt][n8], af, bf[n8]);
        }
    }
    // store M half: rows o, cols h*64 + d
    #pragma unroll
    for (int mt=0;mt<2;mt++){
        int r0 = warp*32 + mt*16 + g;
        int r1 = r0 + 8;
        #pragma unroll
        for (int n8=0;n8<8;n8++){
            int c = h*64 + n8*8 + 2*t4;
            *(__half2*)(g_Mh + ((size_t)b*OD + r0)*QD + c) =
                __floats2half2_rn(acc[mt][n8][0], acc[mt][n8][1]);
            *(__half2*)(g_Mh + ((size_t)b*OD + r1)*QD + c) =
                __floats2half2_rn(acc[mt][n8][2], acc[mt][n8][3]);
        }
    }
}

// ---------------- K5: fused q-proj(fp16) -> softmax(d) -> out GEMM (fp16) ----------------
// grid (64, 32), 256 thr.  smem total = 148480 B
__global__ void __launch_bounds__(256) fused_q_out_mma(
    const float* __restrict__ x, const float* __restrict__ bq,
    const float* __restrict__ bo, float* __restrict__ out)
{
    extern __shared__ __half smh[];
    __half* xs  = smh;                  // [64][264] (phase A, transposed x)
    __half* qs  = smh;                  // [64][520] (phase B/C), aliases xs region
    __half* As  = smh + 33280;          // [2][512][40] phase A; [2][256][40] phase C
    const int nt = blockIdx.x, b = blockIdx.y;
    const int n0 = nt*64;
    const int tid = threadIdx.x;
    const int warp = tid>>5, lane = tid&31;
    const int g = lane>>2, t4 = lane&3;

    // prefetch Wq chunk 0 FIRST (overlaps with synchronous x load below)
    #pragma unroll
    for (int j=0;j<8;j++){
        int s = tid + 256*j;
        int row = s>>2, seg = s&3;
        cpa16(As + row*40 + seg*8, g_Wqh + row*Cc + seg*8);
    }
    CP_COMMIT();

    for (int i = tid; i < 256*16; i += 256) {
        int c = i>>4, n4 = (i&15)*4;
        float4 val = *(const float4*)(x + ((size_t)b*Cc + c)*Nn + n0 + n4);
        xs[(n4+0)*264 + c] = __float2half_rn(val.x);
        xs[(n4+1)*264 + c] = __float2half_rn(val.y);
        xs[(n4+2)*264 + c] = __float2half_rn(val.z);
        xs[(n4+3)*264 + c] = __float2half_rn(val.w);
    }

    // ---- Phase A (fp16): q = Wq @ x ; warp == head, warp tile 64x64 ----
    float acc[4][8][4];
    #pragma unroll
    for (int a=0;a<4;a++)
      #pragma unroll
      for (int c=0;c<8;c++)
        #pragma unroll
        for (int k=0;k<4;k++) acc[a][c][k]=0.f;

    const int NKA = 8;
    for (int kc=0; kc<NKA; kc++){
        if (kc+1 < NKA){
            __half* dst = As + ((kc+1)&1)*20480;
            const __half* src = g_Wqh + (kc+1)*32;
            #pragma unroll
            for (int j=0;j<8;j++){
                int s = tid + 256*j;
                int row = s>>2, seg = s&3;
                cpa16(dst + row*40 + seg*8, src + row*Cc + seg*8);
            }
            CP_COMMIT(); CP_WAIT1();
        } else CP_WAIT0();
        __syncthreads();
        const __half* A0 = As + (kc&1)*20480 + (warp*64)*40;
        #pragma unroll
        for (int sub=0; sub<2; sub++){
            int kl = sub*16 + t4*2;
            int kabs = kc*32 + kl;
            unsigned bf[8][2];
            #pragma unroll
            for (int n8=0;n8<8;n8++){
                int n = n8*8 + g;
                bf[n8][0] = ldh2(xs + n*264 + kabs);
                bf[n8][1] = ldh2(xs + n*264 + kabs + 8);
            }
            #pragma unroll
            for (int mt=0;mt<4;mt++){
                const __half* Ap = A0 + (mt*16 + g)*40 + kl;
                unsigned af[4];
                af[0] = ldh2(Ap);
                af[1] = ldh2(Ap + 8*40);
                af[2] = ldh2(Ap + 8);
                af[3] = ldh2(Ap + 8*40 + 8);
                #pragma unroll
                for (int n8=0;n8<8;n8++) mma16h(acc[mt][n8], af, bf[n8]);
            }
        }
        __syncthreads();
    }

    // ---- prefetch M chunks 0,1 into Msh (As region dead); overlaps softmax ----
    const __half* Mb = g_Mh + (size_t)b*OD*QD;
    __half* Msh = As;                   // [2][256][40]
    #pragma unroll
    for (int j=0;j<4;j++){
        int s = tid + 256*j;
        int row = s>>2, seg = s&3;
        cpa16(Msh + row*40 + seg*8, Mb + row*QD + seg*8);
    }
    CP_COMMIT();
    #pragma unroll
    for (int j=0;j<4;j++){
        int s = tid + 256*j;
        int row = s>>2, seg = s&3;
        cpa16(Msh + 10240 + row*40 + seg*8, Mb + 32 + row*QD + seg*8);
    }
    CP_COMMIT();

    // ---- Phase B: bias + exp + softmax over kd (this warp = one head) ----
    #pragma unroll
    for (int mt=0;mt<4;mt++){
        float b0 = bq[warp*64 + mt*16 + g];
        float b1 = bq[warp*64 + mt*16 + g + 8];
        #pragma unroll
        for (int n8=0;n8<8;n8++){
            acc[mt][n8][0] = __expf(acc[mt][n8][0] + b0);
            acc[mt][n8][1] = __expf(acc[mt][n8][1] + b0);
            acc[mt][n8][2] = __expf(acc[mt][n8][2] + b1);
            acc[mt][n8][3] = __expf(acc[mt][n8][3] + b1);
        }
    }
    float inv[8][2];
    #pragma unroll
    for (int n8=0;n8<8;n8++){
        #pragma unroll
        for (int p=0;p<2;p++){
            float s = 0.f;
            #pragma unroll
            for (int mt=0;mt<4;mt++) s += acc[mt][n8][p] + acc[mt][n8][p+2];
            s += __shfl_xor_sync(0xffffffffu, s, 4);
            s += __shfl_xor_sync(0xffffffffu, s, 8);
            s += __shfl_xor_sync(0xffffffffu, s, 16);
            inv[n8][p] = 1.f/s;
        }
    }
    #pragma unroll
    for (int mt=0;mt<4;mt++){
        int k0 = warp*64 + mt*16 + g;
        #pragma unroll
        for (int n8=0;n8<8;n8++){
            int n = n8*8 + 2*t4;
            qs[n*520 + k0]       = __float2half_rn(acc[mt][n8][0]*inv[n8][0]);
            qs[(n+1)*520 + k0]   = __float2half_rn(acc[mt][n8][1]*inv[n8][1]);
            qs[n*520 + k0+8]     = __float2half_rn(acc[mt][n8][2]*inv[n8][0]);
            qs[(n+1)*520 + k0+8] = __float2half_rn(acc[mt][n8][3]*inv[n8][1]);
        }
    }
    __syncthreads();

    // ---- Phase C (fp16): out = M[b] @ qs ----
    float acc2[4][4][4];
    #pragma unroll
    for (int a=0;a<4;a++)
      #pragma unroll
      for (int c=0;c<4;c++)
        #pragma unroll
        for (int k=0;k<4;k++) acc2[a][c][k]=0.f;

    const int wr = warp>>1, wc = warp&1;
    const int NKC = 16;
    for (int ki=0; ki<NKC; ki++){
        if (ki < NKC-1) CP_WAIT1(); else CP_WAIT0();
        __syncthreads();
        const __half* A0 = Msh + (ki&1)*10240 + (wr*64)*40;
        #pragma unroll
        for (int sub=0; sub<2; sub++){
            int kl = sub*16 + t4*2;
            int kabs = ki*32 + kl;
            unsigned bf[4][2];
            #pragma unroll
            for (int n8=0;n8<4;n8++){
                int n = wc*32 + n8*8 + g;
                bf[n8][0] = ldh2(qs + n*520 + kabs);
                bf[n8][1] = ldh2(qs + n*520 + kabs + 8);
            }
            #pragma unroll
            for (int mt=0;mt<4;mt++){
                const __half* Ap = A0 + (mt*16 + g)*40 + kl;
                unsigned af[4];
                af[0] = ldh2(Ap);
                af[1] = ldh2(Ap + 8*40);
                af[2] = ldh2(Ap + 8);
                af[3] = ldh2(Ap + 8*40 + 8);
                #pragma unroll
                for (int n8=0;n8<4;n8++) mma16h(acc2[mt][n8], af, bf[n8]);
            }
        }
        __syncthreads();
        if (ki + 2 < NKC){
            __half* dst = Msh + (ki&1)*10240;
            const __half* src = Mb + (ki+2)*32;
            #pragma unroll
            for (int j=0;j<4;j++){
                int s = tid + 256*j;
                int row = s>>2, seg = s&3;
                cpa16(dst + row*40 + seg*8, src + row*QD + seg*8);
            }
            CP_COMMIT();
        }
    }
    // epilogue
    #pragma unroll
    for (int mt=0;mt<4;mt++){
        int r0 = wr*64 + mt*16 + g;
        float bo0 = bo[r0], bo1 = bo[r0+8];
        #pragma unroll
        for (int n8=0;n8<4;n8++){
            int c = n0 + wc*32 + n8*8 + 2*t4;
            *(float2*)(out + ((size_t)b*OD + r0)*Nn + c) =
                make_float2(acc2[mt][n8][0]+bo0, acc2[mt][n8][1]+bo0);
            *(float2*)(out + ((size_t)b*OD + r0+8)*Nn + c) =
                make_float2(acc2[mt][n8][2]+bo1, acc2[mt][n8][3]+bo1);
        }
    }
}

// ---------------- launch ----------------
extern "C" void kernel_launch(void* const* d_in, const int* in_sizes, int n_in,
                              void* d_out, int out_size)
{
    const float* x  = (const float*)d_in[0];
    const float* Wq = (const float*)d_in[1];
    const float* bq = (const float*)d_in[2];
    const float* Wk = (const float*)d_in[3];
    const float* bk = (const float*)d_in[4];
    const float* Wv = (const float*)d_in[5];
    const float* bv = (const float*)d_in[6];
    const float* Wo = (const float*)d_in[7];
    const float* bo = (const float*)d_in[8];
    float* out = (float*)d_out;

    round_kernel<<<512, 256>>>(Wq, Wk, Wv, Wo);

    cudaFuncSetAttribute(kv_proj_ctx, cudaFuncAttributeMaxDynamicSharedMemorySize, 88064);
    kv_proj_ctx<<<dim3(32,32), 256, 88064>>>(x, bk, bv);

    m_kernel_h<<<dim3(8,32), 256>>>();

    cudaFuncSetAttribute(fused_q_out_mma, cudaFuncAttributeMaxDynamicSharedMemorySize, 148480);
    fused_q_out_mma<<<dim3(64,32), 256, 148480>>>(x, bq, bo, out);
}